// round 1
// baseline (speedup 1.0000x reference)
#include <cuda_runtime.h>
#include <math.h>

#define DIM 2048
#define NHEADS 16
#define HD 128
#define BATCH 4
#define SEQ 2048
#define MROWS (BATCH*SEQ)   // 8192
#define FLD 132             // HD + 4 pad floats (conflict-free strided LDS)
#define GLD 20              // 16 k-floats + 4 pad

// Scratch (static device allocations — allowed; cudaMalloc is not)
__device__ float g_q [MROWS*DIM];
__device__ float g_k [MROWS*DIM];
__device__ float g_v [MROWS*DIM];
__device__ float g_ao[MROWS*DIM];

// ---------------------------------------------------------------------------
// NT GEMM: C[m][n] = sum_k A[m][k]*B[n][k] (+bias). 128x128 block tile,
// kt=16, 256 threads, 8x8 microtile with strided ownership, reg double-buffer.
// ---------------------------------------------------------------------------
__device__ __forceinline__ void gemm_nt_body(
    const float* __restrict__ A, const float* __restrict__ B,
    float* __restrict__ C, const float* __restrict__ bias,
    int bn, int bm)
{
    __shared__ float As[128 * GLD];
    __shared__ float Bs[128 * GLD];
    const int t  = threadIdx.x;
    const int tr = t >> 4;
    const int tc = t & 15;
    const int lr = t >> 2;          // load row 0..63 (and +64)
    const int lk = (t & 3) << 2;    // k offset 0,4,8,12

    const float* Ap = A + (size_t)(bm * 128 + lr) * DIM + lk;
    const float* Bp = B + (size_t)(bn * 128 + lr) * DIM + lk;
    const size_t rstep = (size_t)64 * DIM;

    float4 a0 = *(const float4*)(Ap);
    float4 a1 = *(const float4*)(Ap + rstep);
    float4 b0 = *(const float4*)(Bp);
    float4 b1 = *(const float4*)(Bp + rstep);

    float acc[8][8];
    #pragma unroll
    for (int i = 0; i < 8; ++i)
        #pragma unroll
        for (int j = 0; j < 8; ++j) acc[i][j] = 0.f;

    *(float4*)&As[lr*GLD + lk]        = a0;
    *(float4*)&As[(lr+64)*GLD + lk]   = a1;
    *(float4*)&Bs[lr*GLD + lk]        = b0;
    *(float4*)&Bs[(lr+64)*GLD + lk]   = b1;
    __syncthreads();

    const int NKT = DIM / 16;
    for (int kt = 0; kt < NKT; ++kt) {
        if (kt + 1 < NKT) {
            const float* Ap2 = Ap + (kt + 1) * 16;
            const float* Bp2 = Bp + (kt + 1) * 16;
            a0 = *(const float4*)(Ap2);
            a1 = *(const float4*)(Ap2 + rstep);
            b0 = *(const float4*)(Bp2);
            b1 = *(const float4*)(Bp2 + rstep);
        }
        #pragma unroll
        for (int k4 = 0; k4 < 4; ++k4) {
            float4 af[8], bf[8];
            #pragma unroll
            for (int i = 0; i < 8; ++i)
                af[i] = *(const float4*)&As[(tr + 16*i)*GLD + k4*4];
            #pragma unroll
            for (int j = 0; j < 8; ++j)
                bf[j] = *(const float4*)&Bs[(tc + 16*j)*GLD + k4*4];
            #pragma unroll
            for (int i = 0; i < 8; ++i)
                #pragma unroll
                for (int j = 0; j < 8; ++j) {
                    acc[i][j] += af[i].x * bf[j].x;
                    acc[i][j] += af[i].y * bf[j].y;
                    acc[i][j] += af[i].z * bf[j].z;
                    acc[i][j] += af[i].w * bf[j].w;
                }
        }
        __syncthreads();
        if (kt + 1 < NKT) {
            *(float4*)&As[lr*GLD + lk]      = a0;
            *(float4*)&As[(lr+64)*GLD + lk] = a1;
            *(float4*)&Bs[lr*GLD + lk]      = b0;
            *(float4*)&Bs[(lr+64)*GLD + lk] = b1;
        }
        __syncthreads();
    }

    const int row0 = bm * 128, col0 = bn * 128;
    #pragma unroll
    for (int i = 0; i < 8; ++i) {
        float* Cp = C + (size_t)(row0 + tr + 16*i) * DIM + col0 + tc;
        #pragma unroll
        for (int j = 0; j < 8; ++j) {
            float v = acc[i][j];
            if (bias) v += bias[col0 + tc + 16*j];
            Cp[16*j] = v;
        }
    }
}

__global__ __launch_bounds__(256) void gemm_qkv_kernel(
    const float* __restrict__ X, const float* __restrict__ Wq,
    const float* __restrict__ Wk, const float* __restrict__ Wv)
{
    const float* W = (blockIdx.z == 0) ? Wq : (blockIdx.z == 1 ? Wk : Wv);
    float*       C = (blockIdx.z == 0) ? g_q : (blockIdx.z == 1 ? g_k : g_v);
    gemm_nt_body(X, W, C, nullptr, blockIdx.x, blockIdx.y);
}

__global__ __launch_bounds__(256) void gemm_out_kernel(
    const float* __restrict__ Wo, const float* __restrict__ bo,
    float* __restrict__ out)
{
    gemm_nt_body(g_ao, Wo, out, bo, blockIdx.x, blockIdx.y);
}

// ---------------------------------------------------------------------------
// RoPE in-place on g_q / g_k. One thread per (row, head, pair).
// ---------------------------------------------------------------------------
__global__ void rope_kernel(int which)
{
    float* buf = which ? g_k : g_q;
    int idx = blockIdx.x * blockDim.x + threadIdx.x;   // < MROWS*1024
    int m   = idx >> 10;
    int rem = idx & 1023;
    int h   = rem >> 6;
    int j   = rem & 63;
    int s   = m & (SEQ - 1);
    // freq = 10000^(-j/64) = 2^(-j*log2(10000)/64)
    float freq = exp2f(-(float)j * 0.20762050593045951f);
    float ang  = (float)s * freq;
    float sn, cs;
    sincosf(ang, &sn, &cs);
    size_t base = (size_t)m * DIM + h * HD + j;
    float t1 = buf[base], t2 = buf[base + 64];
    buf[base]      = t1 * cs - t2 * sn;
    buf[base + 64] = t2 * cs + t1 * sn;
}

// ---------------------------------------------------------------------------
// Causal flash attention, fp32. BM=BN=128, Hd=128, 256 threads, 8x8 microtiles
// with strided ownership (row = tr+16i, col = tc+16j). Online softmax with
// width-16 shuffle reductions. K and V share one smem buffer (sequential use).
// ---------------------------------------------------------------------------
__global__ __launch_bounds__(256, 1) void flash_attn_kernel()
{
    extern __shared__ float sm[];
    float* Qs  = sm;                  // 128*FLD
    float* KVs = sm + 128 * FLD;      // K tile, then V tile
    float* Ps  = sm + 2 * 128 * FLD;  // exp(S) tile

    const int t  = threadIdx.x;
    const int tr = t >> 4;
    const int tc = t & 15;
    const int qt = (int)gridDim.x - 1 - (int)blockIdx.x;  // big-work blocks first
    const int bh = blockIdx.y;
    const int b  = bh >> 4, h = bh & 15;

    const float scale = 0.088388347648318447f;  // 1/sqrt(128)
    const size_t row_base = (size_t)(b * SEQ + qt * 128);
    const float* Qg = g_q + row_base * DIM + h * HD;

    #pragma unroll
    for (int it = 0; it < 16; ++it) {
        int idx = t + it * 256;
        int r = idx >> 5, d4 = (idx & 31) << 2;
        float4 v = *(const float4*)(Qg + (size_t)r * DIM + d4);
        v.x *= scale; v.y *= scale; v.z *= scale; v.w *= scale;
        *(float4*)&Qs[r * FLD + d4] = v;
    }

    float m_i[8], l_i[8], o[8][8];
    #pragma unroll
    for (int i = 0; i < 8; ++i) {
        m_i[i] = -1e30f; l_i[i] = 0.f;
        #pragma unroll
        for (int j = 0; j < 8; ++j) o[i][j] = 0.f;
    }
    __syncthreads();

    for (int jt = 0; jt <= qt; ++jt) {
        const float* Kg = g_k + (size_t)(b * SEQ + jt * 128) * DIM + h * HD;
        #pragma unroll
        for (int it = 0; it < 16; ++it) {
            int idx = t + it * 256;
            int r = idx >> 5, d4 = (idx & 31) << 2;
            *(float4*)&KVs[r * FLD + d4] = *(const float4*)(Kg + (size_t)r * DIM + d4);
        }
        __syncthreads();

        float s[8][8];
        #pragma unroll
        for (int i = 0; i < 8; ++i)
            #pragma unroll
            for (int j = 0; j < 8; ++j) s[i][j] = 0.f;

        #pragma unroll
        for (int d4 = 0; d4 < 32; ++d4) {
            float4 af[8], bf[8];
            #pragma unroll
            for (int i = 0; i < 8; ++i)
                af[i] = *(const float4*)&Qs[(tr + 16*i) * FLD + 4*d4];
            #pragma unroll
            for (int j = 0; j < 8; ++j)
                bf[j] = *(const float4*)&KVs[(tc + 16*j) * FLD + 4*d4];
            #pragma unroll
            for (int i = 0; i < 8; ++i)
                #pragma unroll
                for (int j = 0; j < 8; ++j) {
                    s[i][j] += af[i].x * bf[j].x;
                    s[i][j] += af[i].y * bf[j].y;
                    s[i][j] += af[i].z * bf[j].z;
                    s[i][j] += af[i].w * bf[j].w;
                }
        }

        if (jt == qt) {
            #pragma unroll
            for (int i = 0; i < 8; ++i)
                #pragma unroll
                for (int j = 0; j < 8; ++j)
                    if (tc + 16*j > tr + 16*i) s[i][j] = -1e30f;
        }

        #pragma unroll
        for (int i = 0; i < 8; ++i) {
            float mx = s[i][0];
            #pragma unroll
            for (int j = 1; j < 8; ++j) mx = fmaxf(mx, s[i][j]);
            #pragma unroll
            for (int w = 1; w < 16; w <<= 1)
                mx = fmaxf(mx, __shfl_xor_sync(0xffffffffu, mx, w));
            float mnew = fmaxf(m_i[i], mx);
            float corr = __expf(m_i[i] - mnew);
            float sum = 0.f;
            #pragma unroll
            for (int j = 0; j < 8; ++j) {
                float e = __expf(s[i][j] - mnew);
                s[i][j] = e;
                sum += e;
            }
            #pragma unroll
            for (int w = 1; w < 16; w <<= 1)
                sum += __shfl_xor_sync(0xffffffffu, sum, w);
            l_i[i] = l_i[i] * corr + sum;
            m_i[i] = mnew;
            #pragma unroll
            for (int j = 0; j < 8; ++j) o[i][j] *= corr;
        }

        #pragma unroll
        for (int i = 0; i < 8; ++i)
            #pragma unroll
            for (int j = 0; j < 8; ++j)
                Ps[(tr + 16*i) * FLD + tc + 16*j] = s[i][j];
        __syncthreads();  // P visible; K fully consumed

        const float* Vg = g_v + (size_t)(b * SEQ + jt * 128) * DIM + h * HD;
        #pragma unroll
        for (int it = 0; it < 16; ++it) {
            int idx = t + it * 256;
            int r = idx >> 5, d4 = (idx & 31) << 2;
            *(float4*)&KVs[r * FLD + d4] = *(const float4*)(Vg + (size_t)r * DIM + d4);
        }
        __syncthreads();

        #pragma unroll
        for (int c4 = 0; c4 < 32; ++c4) {
            float4 p4[8];
            #pragma unroll
            for (int i = 0; i < 8; ++i)
                p4[i] = *(const float4*)&Ps[(tr + 16*i) * FLD + 4*c4];
            #pragma unroll
            for (int cc = 0; cc < 4; ++cc) {
                float vf[8];
                #pragma unroll
                for (int j = 0; j < 8; ++j)
                    vf[j] = KVs[(4*c4 + cc) * FLD + tc + 16*j];
                #pragma unroll
                for (int i = 0; i < 8; ++i) {
                    float p = (cc == 0) ? p4[i].x : (cc == 1) ? p4[i].y
                             : (cc == 2) ? p4[i].z : p4[i].w;
                    #pragma unroll
                    for (int j = 0; j < 8; ++j) o[i][j] += p * vf[j];
                }
            }
        }
        __syncthreads();  // V consumed before next K load
    }

    float* Og = g_ao + row_base * DIM + h * HD;
    #pragma unroll
    for (int i = 0; i < 8; ++i) {
        float inv = 1.f / l_i[i];
        #pragma unroll
        for (int j = 0; j < 8; ++j)
            Og[(size_t)(tr + 16*i) * DIM + tc + 16*j] = o[i][j] * inv;
    }
}

// ---------------------------------------------------------------------------
extern "C" void kernel_launch(void* const* d_in, const int* in_sizes, int n_in,
                              void* d_out, int out_size)
{
    const float* x  = (const float*)d_in[0];
    const float* Wq = (const float*)d_in[1];
    const float* Wk = (const float*)d_in[2];
    const float* Wv = (const float*)d_in[3];
    const float* Wo = (const float*)d_in[4];
    const float* bo = (const float*)d_in[5];
    float* out = (float*)d_out;

    const int flash_smem = 3 * 128 * FLD * sizeof(float);  // 202752 B
    cudaFuncSetAttribute(flash_attn_kernel,
        cudaFuncAttributeMaxDynamicSharedMemorySize, flash_smem);

    dim3 gq(DIM/128, MROWS/128, 3);
    gemm_qkv_kernel<<<gq, 256>>>(x, Wq, Wk, Wv);

    int rope_blocks = (MROWS * 1024) / 256;
    rope_kernel<<<rope_blocks, 256>>>(0);
    rope_kernel<<<rope_blocks, 256>>>(1);

    dim3 gf(SEQ/128, BATCH*NHEADS);
    flash_attn_kernel<<<gf, 256, flash_smem>>>();

    dim3 go(DIM/128, MROWS/128);
    gemm_out_kernel<<<go, 256>>>(Wo, bo, out);
}

// round 3
// speedup vs baseline: 1.4853x; 1.4853x over previous
#include <cuda_runtime.h>
#include <cuda_bf16.h>
#include <math.h>
#include <stdint.h>

#define DIM 2048
#define NHEADS 16
#define HD 128
#define BATCH 4
#define SEQ 2048
#define MROWS (BATCH*SEQ)   // 8192
#define FLD 132             // flash smem row pad (floats)
#define DD (DIM*DIM)

#define KT 32               // bf16 K per smem tile
#define NKI (DIM/KT)        // 64 k-iterations
#define AROW 40             // smem row: 32 bf16 + 8 pad  (80 bytes)
#define TILE_E (128*AROW)   // elems per tile (5120)
#define TILE_BYTES (TILE_E*2)  // 10240
#define GEMM_SMEM (8*TILE_BYTES)  // 2 buf x 4 tiles = 81920

// ---------------- scratch (static device memory; no allocs) ----------------
__device__ float g_q [MROWS*DIM];
__device__ float g_k [MROWS*DIM];
__device__ float g_v [MROWS*DIM];
__device__ __nv_bfloat16 g_xh[MROWS*DIM];
__device__ __nv_bfloat16 g_xl[MROWS*DIM];
__device__ __nv_bfloat16 g_wh[4*DD];
__device__ __nv_bfloat16 g_wl[4*DD];
__device__ __nv_bfloat16 g_aoh[MROWS*DIM];
__device__ __nv_bfloat16 g_aol[MROWS*DIM];

// ---------------- bf16 hi/lo split conversion ----------------
// sel: 0 -> x into g_xh/g_xl ; 1..4 -> weight slot (sel-1) into g_wh/g_wl
__global__ void split_bf16_kernel(const float* __restrict__ in, int sel, int n4)
{
    int i = blockIdx.x * blockDim.x + threadIdx.x;
    if (i >= n4) return;
    __nv_bfloat16* oh;
    __nv_bfloat16* ol;
    if (sel == 0) { oh = g_xh; ol = g_xl; }
    else { size_t off = (size_t)(sel - 1) * DD; oh = g_wh + off; ol = g_wl + off; }
    float4 v = ((const float4*)in)[i];
    __nv_bfloat16 h0 = __float2bfloat16(v.x);
    __nv_bfloat16 h1 = __float2bfloat16(v.y);
    __nv_bfloat16 h2 = __float2bfloat16(v.z);
    __nv_bfloat16 h3 = __float2bfloat16(v.w);
    __nv_bfloat162* ohp = (__nv_bfloat162*)oh;
    __nv_bfloat162* olp = (__nv_bfloat162*)ol;
    ohp[i*2+0] = __nv_bfloat162(h0, h1);
    ohp[i*2+1] = __nv_bfloat162(h2, h3);
    olp[i*2+0] = __nv_bfloat162(__float2bfloat16(v.x - __bfloat162float(h0)),
                                __float2bfloat16(v.y - __bfloat162float(h1)));
    olp[i*2+1] = __nv_bfloat162(__float2bfloat16(v.z - __bfloat162float(h2)),
                                __float2bfloat16(v.w - __bfloat162float(h3)));
}

// ---------------- mma.sync bf16 helper ----------------
__device__ __forceinline__ void mma16816(float* d, const uint32_t* a, const uint32_t* b)
{
    asm volatile(
        "mma.sync.aligned.m16n8k16.row.col.f32.bf16.bf16.f32 "
        "{%0,%1,%2,%3}, {%4,%5,%6,%7}, {%8,%9}, {%0,%1,%2,%3};"
        : "+f"(d[0]), "+f"(d[1]), "+f"(d[2]), "+f"(d[3])
        : "r"(a[0]), "r"(a[1]), "r"(a[2]), "r"(a[3]), "r"(b[0]), "r"(b[1]));
}

// ---------------- split-bf16 NT GEMM on mma.sync ----------------
// C[m][n] = sum_k A[m][k]*B[n][k] (+bias). 128x128 CTA tile, 8 warps (2m x 4n),
// warp tile 64x32 (4 x m16 tiles, 4 x n8 tiles). 3-term split into fp32 accum.
__device__ __forceinline__ void gemm_mma_body(
    const __nv_bfloat16* __restrict__ Ah, const __nv_bfloat16* __restrict__ Al,
    const __nv_bfloat16* __restrict__ Bh, const __nv_bfloat16* __restrict__ Bl,
    float* __restrict__ C, const float* __restrict__ bias, int bn, int bm)
{
    extern __shared__ __nv_bfloat16 sm[];
    const int t    = threadIdx.x;
    const int wid  = t >> 5;
    const int lane = t & 31;
    const int g    = lane >> 2;
    const int tg   = lane & 3;
    const int mo   = (wid & 1) * 64;
    const int no   = (wid >> 1) * 32;

    const __nv_bfloat16* srcs[4] = { Ah, Al, Bh, Bl };
    const int rb[4] = { bm*128, bm*128, bn*128, bn*128 };

    float acc[4][4][4];
    #pragma unroll
    for (int mt = 0; mt < 4; ++mt)
        #pragma unroll
        for (int nt = 0; nt < 4; ++nt)
            #pragma unroll
            for (int r = 0; r < 4; ++r) acc[mt][nt][r] = 0.f;

    uint4 stg[8];

    // prologue: k-tile 0 -> buf 0
    #pragma unroll
    for (int q = 0; q < 4; ++q)
        #pragma unroll
        for (int i = 0; i < 2; ++i) {
            int s = t + 256*i; int r = s >> 2, v = s & 3;
            stg[q*2+i] = *(const uint4*)(srcs[q] + (size_t)(rb[q]+r)*DIM + v*8);
        }
    #pragma unroll
    for (int q = 0; q < 4; ++q)
        #pragma unroll
        for (int i = 0; i < 2; ++i) {
            int s = t + 256*i; int r = s >> 2, v = s & 3;
            *(uint4*)((char*)(sm + q*TILE_E) + r*80 + v*16) = stg[q*2+i];
        }
    __syncthreads();

    for (int kt = 0; kt < NKI; ++kt) {
        if (kt + 1 < NKI) {
            const int ko = (kt + 1) * KT;
            #pragma unroll
            for (int q = 0; q < 4; ++q)
                #pragma unroll
                for (int i = 0; i < 2; ++i) {
                    int s = t + 256*i; int r = s >> 2, v = s & 3;
                    stg[q*2+i] = *(const uint4*)(srcs[q] + (size_t)(rb[q]+r)*DIM + ko + v*8);
                }
        }

        const __nv_bfloat16* buf = sm + (kt & 1) * 4 * TILE_E;
        const __nv_bfloat16* tAh = buf;
        const __nv_bfloat16* tAl = buf + TILE_E;
        const __nv_bfloat16* tBh = buf + 2*TILE_E;
        const __nv_bfloat16* tBl = buf + 3*TILE_E;

        #pragma unroll
        for (int ks = 0; ks < 2; ++ks) {
            uint32_t fAh[4][4], fAl[4][4], fBh[4][2], fBl[4][2];
            #pragma unroll
            for (int mt = 0; mt < 4; ++mt) {
                int row = mo + mt*16 + g;
                const __nv_bfloat16* p = tAh + row*AROW + ks*16 + 2*tg;
                fAh[mt][0] = *(const uint32_t*)(p);
                fAh[mt][1] = *(const uint32_t*)(p + 8*AROW);
                fAh[mt][2] = *(const uint32_t*)(p + 8);
                fAh[mt][3] = *(const uint32_t*)(p + 8*AROW + 8);
                const __nv_bfloat16* q = tAl + row*AROW + ks*16 + 2*tg;
                fAl[mt][0] = *(const uint32_t*)(q);
                fAl[mt][1] = *(const uint32_t*)(q + 8*AROW);
                fAl[mt][2] = *(const uint32_t*)(q + 8);
                fAl[mt][3] = *(const uint32_t*)(q + 8*AROW + 8);
            }
            #pragma unroll
            for (int nt = 0; nt < 4; ++nt) {
                int row = no + nt*8 + g;
                const __nv_bfloat16* p = tBh + row*AROW + ks*16 + 2*tg;
                fBh[nt][0] = *(const uint32_t*)(p);
                fBh[nt][1] = *(const uint32_t*)(p + 8);
                const __nv_bfloat16* q = tBl + row*AROW + ks*16 + 2*tg;
                fBl[nt][0] = *(const uint32_t*)(q);
                fBl[nt][1] = *(const uint32_t*)(q + 8);
            }
            #pragma unroll
            for (int mt = 0; mt < 4; ++mt)
                #pragma unroll
                for (int nt = 0; nt < 4; ++nt) {
                    mma16816(acc[mt][nt], fAh[mt], fBh[nt]);
                    mma16816(acc[mt][nt], fAh[mt], fBl[nt]);
                    mma16816(acc[mt][nt], fAl[mt], fBh[nt]);
                }
        }
        __syncthreads();

        if (kt + 1 < NKI) {
            __nv_bfloat16* dst = sm + ((kt + 1) & 1) * 4 * TILE_E;
            #pragma unroll
            for (int q = 0; q < 4; ++q)
                #pragma unroll
                for (int i = 0; i < 2; ++i) {
                    int s = t + 256*i; int r = s >> 2, v = s & 3;
                    *(uint4*)((char*)(dst + q*TILE_E) + r*80 + v*16) = stg[q*2+i];
                }
        }
        __syncthreads();
    }

    // epilogue: direct gmem stores (float2 per fragment row)
    const int row0 = bm*128, col0 = bn*128;
    #pragma unroll
    for (int mt = 0; mt < 4; ++mt) {
        int r = row0 + mo + mt*16 + g;
        #pragma unroll
        for (int nt = 0; nt < 4; ++nt) {
            int c = col0 + no + nt*8 + 2*tg;
            float b0 = 0.f, b1 = 0.f;
            if (bias) { b0 = bias[c]; b1 = bias[c+1]; }
            float2 v0 = make_float2(acc[mt][nt][0] + b0, acc[mt][nt][1] + b1);
            float2 v1 = make_float2(acc[mt][nt][2] + b0, acc[mt][nt][3] + b1);
            *(float2*)&C[(size_t)r * DIM + c]       = v0;
            *(float2*)&C[(size_t)(r+8) * DIM + c]   = v1;
        }
    }
}

__global__ __launch_bounds__(256, 1) void qkv_mma_kernel()
{
    const int z = blockIdx.z;
    float* C = (z == 0) ? g_q : (z == 1 ? g_k : g_v);
    gemm_mma_body(g_xh, g_xl, g_wh + (size_t)z*DD, g_wl + (size_t)z*DD,
                  C, nullptr, blockIdx.x, blockIdx.y);
}

__global__ __launch_bounds__(256, 1) void out_mma_kernel(
    float* __restrict__ out, const float* __restrict__ bo)
{
    gemm_mma_body(g_aoh, g_aol, g_wh + (size_t)3*DD, g_wl + (size_t)3*DD,
                  out, bo, blockIdx.x, blockIdx.y);
}

// ---------------- RoPE (in-place on fp32 q/k) ----------------
__global__ void rope_kernel(int which)
{
    float* buf = which ? g_k : g_q;
    int idx = blockIdx.x * blockDim.x + threadIdx.x;
    int m   = idx >> 10;
    int rem = idx & 1023;
    int h   = rem >> 6;
    int j   = rem & 63;
    int s   = m & (SEQ - 1);
    float freq = exp2f(-(float)j * 0.20762050593045951f);
    float ang  = (float)s * freq;
    float sn, cs;
    sincosf(ang, &sn, &cs);
    size_t base = (size_t)m * DIM + h * HD + j;
    float t1 = buf[base], t2 = buf[base + 64];
    buf[base]      = t1 * cs - t2 * sn;
    buf[base + 64] = t2 * cs + t1 * sn;
}

// ---------------- causal flash attention (fp32 core) ----------------
__global__ __launch_bounds__(256, 1) void flash_attn_kernel()
{
    extern __shared__ float smf[];
    float* Qs  = smf;
    float* KVs = smf + 128 * FLD;
    float* Ps  = smf + 2 * 128 * FLD;

    const int t  = threadIdx.x;
    const int tr = t >> 4;
    const int tc = t & 15;
    const int qt = (int)gridDim.x - 1 - (int)blockIdx.x;
    const int bh = blockIdx.y;
    const int b  = bh >> 4, h = bh & 15;

    const float scale = 0.088388347648318447f;
    const size_t row_base = (size_t)(b * SEQ + qt * 128);
    const float* Qg = g_q + row_base * DIM + h * HD;

    #pragma unroll
    for (int it = 0; it < 16; ++it) {
        int idx = t + it * 256;
        int r = idx >> 5, d4 = (idx & 31) << 2;
        float4 v = *(const float4*)(Qg + (size_t)r * DIM + d4);
        v.x *= scale; v.y *= scale; v.z *= scale; v.w *= scale;
        *(float4*)&Qs[r * FLD + d4] = v;
    }

    float m_i[8], l_i[8], o[8][8];
    #pragma unroll
    for (int i = 0; i < 8; ++i) {
        m_i[i] = -1e30f; l_i[i] = 0.f;
        #pragma unroll
        for (int j = 0; j < 8; ++j) o[i][j] = 0.f;
    }
    __syncthreads();

    for (int jt = 0; jt <= qt; ++jt) {
        const float* Kg = g_k + (size_t)(b * SEQ + jt * 128) * DIM + h * HD;
        #pragma unroll
        for (int it = 0; it < 16; ++it) {
            int idx = t + it * 256;
            int r = idx >> 5, d4 = (idx & 31) << 2;
            *(float4*)&KVs[r * FLD + d4] = *(const float4*)(Kg + (size_t)r * DIM + d4);
        }
        __syncthreads();

        float s[8][8];
        #pragma unroll
        for (int i = 0; i < 8; ++i)
            #pragma unroll
            for (int j = 0; j < 8; ++j) s[i][j] = 0.f;

        #pragma unroll
        for (int d4 = 0; d4 < 32; ++d4) {
            float4 af[8], bf[8];
            #pragma unroll
            for (int i = 0; i < 8; ++i)
                af[i] = *(const float4*)&Qs[(tr + 16*i) * FLD + 4*d4];
            #pragma unroll
            for (int j = 0; j < 8; ++j)
                bf[j] = *(const float4*)&KVs[(tc + 16*j) * FLD + 4*d4];
            #pragma unroll
            for (int i = 0; i < 8; ++i)
                #pragma unroll
                for (int j = 0; j < 8; ++j) {
                    s[i][j] += af[i].x * bf[j].x;
                    s[i][j] += af[i].y * bf[j].y;
                    s[i][j] += af[i].z * bf[j].z;
                    s[i][j] += af[i].w * bf[j].w;
                }
        }

        if (jt == qt) {
            #pragma unroll
            for (int i = 0; i < 8; ++i)
                #pragma unroll
                for (int j = 0; j < 8; ++j)
                    if (tc + 16*j > tr + 16*i) s[i][j] = -1e30f;
        }

        #pragma unroll
        for (int i = 0; i < 8; ++i) {
            float mx = s[i][0];
            #pragma unroll
            for (int j = 1; j < 8; ++j) mx = fmaxf(mx, s[i][j]);
            #pragma unroll
            for (int w = 1; w < 16; w <<= 1)
                mx = fmaxf(mx, __shfl_xor_sync(0xffffffffu, mx, w));
            float mnew = fmaxf(m_i[i], mx);
            float corr = __expf(m_i[i] - mnew);
            float sum = 0.f;
            #pragma unroll
            for (int j = 0; j < 8; ++j) {
                float e = __expf(s[i][j] - mnew);
                s[i][j] = e;
                sum += e;
            }
            #pragma unroll
            for (int w = 1; w < 16; w <<= 1)
                sum += __shfl_xor_sync(0xffffffffu, sum, w);
            l_i[i] = l_i[i] * corr + sum;
            m_i[i] = mnew;
            #pragma unroll
            for (int j = 0; j < 8; ++j) o[i][j] *= corr;
        }

        #pragma unroll
        for (int i = 0; i < 8; ++i)
            #pragma unroll
            for (int j = 0; j < 8; ++j)
                Ps[(tr + 16*i) * FLD + tc + 16*j] = s[i][j];
        __syncthreads();

        const float* Vg = g_v + (size_t)(b * SEQ + jt * 128) * DIM + h * HD;
        #pragma unroll
        for (int it = 0; it < 16; ++it) {
            int idx = t + it * 256;
            int r = idx >> 5, d4 = (idx & 31) << 2;
            *(float4*)&KVs[r * FLD + d4] = *(const float4*)(Vg + (size_t)r * DIM + d4);
        }
        __syncthreads();

        #pragma unroll
        for (int c4 = 0; c4 < 32; ++c4) {
            float4 p4[8];
            #pragma unroll
            for (int i = 0; i < 8; ++i)
                p4[i] = *(const float4*)&Ps[(tr + 16*i) * FLD + 4*c4];
            #pragma unroll
            for (int cc = 0; cc < 4; ++cc) {
                float vf[8];
                #pragma unroll
                for (int j = 0; j < 8; ++j)
                    vf[j] = KVs[(4*c4 + cc) * FLD + tc + 16*j];
                #pragma unroll
                for (int i = 0; i < 8; ++i) {
                    float p = (cc == 0) ? p4[i].x : (cc == 1) ? p4[i].y
                             : (cc == 2) ? p4[i].z : p4[i].w;
                    #pragma unroll
                    for (int j = 0; j < 8; ++j) o[i][j] += p * vf[j];
                }
            }
        }
        __syncthreads();
    }

    // epilogue: bf16 hi/lo split output for the out-projection GEMM
    __nv_bfloat16* Oh = g_aoh + row_base * DIM + h * HD;
    __nv_bfloat16* Ol = g_aol + row_base * DIM + h * HD;
    #pragma unroll
    for (int i = 0; i < 8; ++i) {
        float inv = 1.f / l_i[i];
        #pragma unroll
        for (int j = 0; j < 8; ++j) {
            size_t idx = (size_t)(tr + 16*i) * DIM + tc + 16*j;
            float v = o[i][j] * inv;
            __nv_bfloat16 hh = __float2bfloat16(v);
            Oh[idx] = hh;
            Ol[idx] = __float2bfloat16(v - __bfloat162float(hh));
        }
    }
}

// ---------------------------------------------------------------------------
extern "C" void kernel_launch(void* const* d_in, const int* in_sizes, int n_in,
                              void* d_out, int out_size)
{
    const float* x  = (const float*)d_in[0];
    const float* Wq = (const float*)d_in[1];
    const float* Wk = (const float*)d_in[2];
    const float* Wv = (const float*)d_in[3];
    const float* Wo = (const float*)d_in[4];
    const float* bo = (const float*)d_in[5];
    float* out = (float*)d_out;

    const int flash_smem = 3 * 128 * FLD * sizeof(float);
    cudaFuncSetAttribute(flash_attn_kernel,
        cudaFuncAttributeMaxDynamicSharedMemorySize, flash_smem);
    cudaFuncSetAttribute(qkv_mma_kernel,
        cudaFuncAttributeMaxDynamicSharedMemorySize, GEMM_SMEM);
    cudaFuncSetAttribute(out_mma_kernel,
        cudaFuncAttributeMaxDynamicSharedMemorySize, GEMM_SMEM);

    // bf16 hi/lo splits
    split_bf16_kernel<<<(MROWS*DIM/4)/256, 256>>>(x,  0, MROWS*DIM/4);
    split_bf16_kernel<<<(DD/4)/256, 256>>>(Wq, 1, DD/4);
    split_bf16_kernel<<<(DD/4)/256, 256>>>(Wk, 2, DD/4);
    split_bf16_kernel<<<(DD/4)/256, 256>>>(Wv, 3, DD/4);
    split_bf16_kernel<<<(DD/4)/256, 256>>>(Wo, 4, DD/4);

    // QKV projections (tensor cores via mma.sync)
    dim3 gq(DIM/128, MROWS/128, 3);
    qkv_mma_kernel<<<gq, 256, GEMM_SMEM>>>();

    // RoPE
    int rope_blocks = (MROWS * 1024) / 256;
    rope_kernel<<<rope_blocks, 256>>>(0);
    rope_kernel<<<rope_blocks, 256>>>(1);

    // flash attention (fp32)
    dim3 gf(SEQ/128, BATCH*NHEADS);
    flash_attn_kernel<<<gf, 256, flash_smem>>>();

    // output projection (tensor cores via mma.sync)
    dim3 go(DIM/128, MROWS/128);
    out_mma_kernel<<<go, 256, GEMM_SMEM>>>(out, bo);
}

// round 4
// speedup vs baseline: 2.7390x; 1.8441x over previous
#include <cuda_runtime.h>
#include <cuda_bf16.h>
#include <math.h>
#include <stdint.h>

#define DIM 2048
#define NHEADS 16
#define HD 128
#define BATCH 4
#define SEQ 2048
#define MROWS (BATCH*SEQ)   // 8192
#define DD (DIM*DIM)

// GEMM tiling
#define KT 32               // bf16 K per smem tile
#define NKI (DIM/KT)        // 64 k-iterations
#define AROW 40             // smem row: 32 bf16 + 8 pad (80 B)
#define TILE_E (128*AROW)
#define TILE_BYTES (TILE_E*2)          // 10240
#define GEMM_SMEM (8*TILE_BYTES)       // 81920

// flash smem
#define SR 136                          // 128 + 8 pad bf16
#define FT_E (128*SR)                   // 17408 elems
#define FT_B (FT_E*2)                   // 34816 bytes
#define FLASH_SMEM (6*FT_B)             // 208896

// ---------------- scratch (static device memory) ----------------
__device__ float g_q [MROWS*DIM];
__device__ float g_k [MROWS*DIM];
__device__ float g_v [MROWS*DIM];
__device__ __nv_bfloat16 g_xh[MROWS*DIM];
__device__ __nv_bfloat16 g_xl[MROWS*DIM];
__device__ __nv_bfloat16 g_wh[4*DD];
__device__ __nv_bfloat16 g_wl[4*DD];
__device__ __nv_bfloat16 g_aoh[MROWS*DIM];
__device__ __nv_bfloat16 g_aol[MROWS*DIM];
__device__ __nv_bfloat16 g_qh[MROWS*DIM];
__device__ __nv_bfloat16 g_ql[MROWS*DIM];
__device__ __nv_bfloat16 g_kh[MROWS*DIM];
__device__ __nv_bfloat16 g_kl[MROWS*DIM];
__device__ __nv_bfloat16 g_vth[MROWS*DIM];   // [bh][d][s]
__device__ __nv_bfloat16 g_vtl[MROWS*DIM];

// ---------------- helpers ----------------
__device__ __forceinline__ uint32_t smem_u32(const void* p) {
    uint32_t a;
    asm("{ .reg .u64 t; cvta.to.shared.u64 t, %1; cvt.u32.u64 %0, t; }" : "=r"(a) : "l"(p));
    return a;
}
#define LDSM4(r0,r1,r2,r3,addr) \
    asm volatile("ldmatrix.sync.aligned.m8n8.x4.shared.b16 {%0,%1,%2,%3}, [%4];" \
        : "=r"(r0), "=r"(r1), "=r"(r2), "=r"(r3) : "r"(addr))

__device__ __forceinline__ void mma16816(float* d, const uint32_t* a, const uint32_t* b)
{
    asm volatile(
        "mma.sync.aligned.m16n8k16.row.col.f32.bf16.bf16.f32 "
        "{%0,%1,%2,%3}, {%4,%5,%6,%7}, {%8,%9}, {%0,%1,%2,%3};"
        : "+f"(d[0]), "+f"(d[1]), "+f"(d[2]), "+f"(d[3])
        : "r"(a[0]), "r"(a[1]), "r"(a[2]), "r"(a[3]), "r"(b[0]), "r"(b[1]));
}

__device__ __forceinline__ uint32_t pack_bf(float x, float y) {
    __nv_bfloat162 p = __floats2bfloat162_rn(x, y);
    return *(uint32_t*)&p;
}
__device__ __forceinline__ void split2(float x, float y, uint32_t& h, uint32_t& l) {
    __nv_bfloat16 hx = __float2bfloat16(x), hy = __float2bfloat16(y);
    __nv_bfloat162 hp(hx, hy);
    h = *(uint32_t*)&hp;
    __nv_bfloat162 lp(__float2bfloat16(x - __bfloat162float(hx)),
                      __float2bfloat16(y - __bfloat162float(hy)));
    l = *(uint32_t*)&lp;
}

// ---------------- bf16 hi/lo split (x and weights) ----------------
__global__ void split_bf16_kernel(const float* __restrict__ in, int sel, int n4)
{
    int i = blockIdx.x * blockDim.x + threadIdx.x;
    if (i >= n4) return;
    __nv_bfloat16 *oh, *ol;
    if (sel == 0) { oh = g_xh; ol = g_xl; }
    else { size_t off = (size_t)(sel - 1) * DD; oh = g_wh + off; ol = g_wl + off; }
    float4 v = ((const float4*)in)[i];
    __nv_bfloat16 h0 = __float2bfloat16(v.x);
    __nv_bfloat16 h1 = __float2bfloat16(v.y);
    __nv_bfloat16 h2 = __float2bfloat16(v.z);
    __nv_bfloat16 h3 = __float2bfloat16(v.w);
    __nv_bfloat162* ohp = (__nv_bfloat162*)oh;
    __nv_bfloat162* olp = (__nv_bfloat162*)ol;
    ohp[i*2+0] = __nv_bfloat162(h0, h1);
    ohp[i*2+1] = __nv_bfloat162(h2, h3);
    olp[i*2+0] = __nv_bfloat162(__float2bfloat16(v.x - __bfloat162float(h0)),
                                __float2bfloat16(v.y - __bfloat162float(h1)));
    olp[i*2+1] = __nv_bfloat162(__float2bfloat16(v.z - __bfloat162float(h2)),
                                __float2bfloat16(v.w - __bfloat162float(h3)));
}

// ---------------- split-bf16 NT GEMM on mma.sync + ldmatrix ----------------
__device__ __forceinline__ void gemm_mma_body(
    const __nv_bfloat16* __restrict__ Ah, const __nv_bfloat16* __restrict__ Al,
    const __nv_bfloat16* __restrict__ Bh, const __nv_bfloat16* __restrict__ Bl,
    float* __restrict__ C, const float* __restrict__ bias, int bn, int bm)
{
    extern __shared__ __nv_bfloat16 sm[];
    const uint32_t su = smem_u32(sm);
    const int t    = threadIdx.x;
    const int wid  = t >> 5;
    const int lane = t & 31;
    const int g    = lane >> 2;
    const int tg   = lane & 3;
    const int mo   = (wid & 1) * 64;
    const int no   = (wid >> 1) * 32;

    const __nv_bfloat16* srcs[4] = { Ah, Al, Bh, Bl };
    const int rb[4] = { bm*128, bm*128, bn*128, bn*128 };

    // ldmatrix per-lane address components (in elements)
    const int a_r = (lane & 15);
    const int a_c = (lane >> 4) << 3;
    const int b_r = ((lane >> 4) << 3) + (lane & 7);
    const int b_c = ((lane >> 3) & 1) << 3;

    float acc[4][4][4];
    #pragma unroll
    for (int mt = 0; mt < 4; ++mt)
        #pragma unroll
        for (int nt = 0; nt < 4; ++nt)
            #pragma unroll
            for (int r = 0; r < 4; ++r) acc[mt][nt][r] = 0.f;

    uint4 stg[8];

    #pragma unroll
    for (int q = 0; q < 4; ++q)
        #pragma unroll
        for (int i = 0; i < 2; ++i) {
            int s = t + 256*i; int r = s >> 2, v = s & 3;
            stg[q*2+i] = *(const uint4*)(srcs[q] + (size_t)(rb[q]+r)*DIM + v*8);
        }
    #pragma unroll
    for (int q = 0; q < 4; ++q)
        #pragma unroll
        for (int i = 0; i < 2; ++i) {
            int s = t + 256*i; int r = s >> 2, v = s & 3;
            *(uint4*)((char*)(sm + q*TILE_E) + r*80 + v*16) = stg[q*2+i];
        }
    __syncthreads();

    for (int kt = 0; kt < NKI; ++kt) {
        if (kt + 1 < NKI) {
            const int ko = (kt + 1) * KT;
            #pragma unroll
            for (int q = 0; q < 4; ++q)
                #pragma unroll
                for (int i = 0; i < 2; ++i) {
                    int s = t + 256*i; int r = s >> 2, v = s & 3;
                    stg[q*2+i] = *(const uint4*)(srcs[q] + (size_t)(rb[q]+r)*DIM + ko + v*8);
                }
        }

        const uint32_t buf = su + (kt & 1) * 4 * TILE_BYTES;
        const uint32_t tAh = buf;
        const uint32_t tAl = buf + TILE_BYTES;
        const uint32_t tBh = buf + 2*TILE_BYTES;
        const uint32_t tBl = buf + 3*TILE_BYTES;

        #pragma unroll
        for (int ks = 0; ks < 2; ++ks) {
            uint32_t aH[4][4], aL[4][4], bH[2][4], bL[2][4];
            #pragma unroll
            for (int mt = 0; mt < 4; ++mt) {
                uint32_t off = 2*((mo + mt*16 + a_r)*AROW + ks*16 + a_c);
                LDSM4(aH[mt][0], aH[mt][1], aH[mt][2], aH[mt][3], tAh + off);
                LDSM4(aL[mt][0], aL[mt][1], aL[mt][2], aL[mt][3], tAl + off);
            }
            #pragma unroll
            for (int np = 0; np < 2; ++np) {
                uint32_t off = 2*((no + np*16 + b_r)*AROW + ks*16 + b_c);
                LDSM4(bH[np][0], bH[np][1], bH[np][2], bH[np][3], tBh + off);
                LDSM4(bL[np][0], bL[np][1], bL[np][2], bL[np][3], tBl + off);
            }
            #pragma unroll
            for (int mt = 0; mt < 4; ++mt)
                #pragma unroll
                for (int np = 0; np < 2; ++np) {
                    mma16816(acc[mt][2*np],   aH[mt], &bH[np][0]);
                    mma16816(acc[mt][2*np],   aH[mt], &bL[np][0]);
                    mma16816(acc[mt][2*np],   aL[mt], &bH[np][0]);
                    mma16816(acc[mt][2*np+1], aH[mt], &bH[np][2]);
                    mma16816(acc[mt][2*np+1], aH[mt], &bL[np][2]);
                    mma16816(acc[mt][2*np+1], aL[mt], &bH[np][2]);
                }
        }
        __syncthreads();

        if (kt + 1 < NKI) {
            __nv_bfloat16* dst = sm + ((kt + 1) & 1) * 4 * TILE_E;
            #pragma unroll
            for (int q = 0; q < 4; ++q)
                #pragma unroll
                for (int i = 0; i < 2; ++i) {
                    int s = t + 256*i; int r = s >> 2, v = s & 3;
                    *(uint4*)((char*)(dst + q*TILE_E) + r*80 + v*16) = stg[q*2+i];
                }
        }
        __syncthreads();
    }

    const int row0 = bm*128, col0 = bn*128;
    #pragma unroll
    for (int mt = 0; mt < 4; ++mt) {
        int r = row0 + mo + mt*16 + g;
        #pragma unroll
        for (int nt = 0; nt < 4; ++nt) {
            int c = col0 + no + nt*8 + 2*tg;
            float b0 = 0.f, b1 = 0.f;
            if (bias) { b0 = bias[c]; b1 = bias[c+1]; }
            float2 v0 = make_float2(acc[mt][nt][0] + b0, acc[mt][nt][1] + b1);
            float2 v1 = make_float2(acc[mt][nt][2] + b0, acc[mt][nt][3] + b1);
            *(float2*)&C[(size_t)r * DIM + c]     = v0;
            *(float2*)&C[(size_t)(r+8) * DIM + c] = v1;
        }
    }
}

__global__ __launch_bounds__(256, 1) void qkv_mma_kernel()
{
    const int z = blockIdx.z;
    float* C = (z == 0) ? g_q : (z == 1 ? g_k : g_v);
    gemm_mma_body(g_xh, g_xl, g_wh + (size_t)z*DD, g_wl + (size_t)z*DD,
                  C, nullptr, blockIdx.x, blockIdx.y);
}

__global__ __launch_bounds__(256, 1) void out_mma_kernel(
    float* __restrict__ out, const float* __restrict__ bo)
{
    gemm_mma_body(g_aoh, g_aol, g_wh + (size_t)3*DD, g_wl + (size_t)3*DD,
                  out, bo, blockIdx.x, blockIdx.y);
}

// ---------------- RoPE + bf16 split (q: scaled) ----------------
__global__ void rope_split_kernel(int which)
{
    const float* src = which ? g_k : g_q;
    __nv_bfloat16* oh = which ? g_kh : g_qh;
    __nv_bfloat16* ol = which ? g_kl : g_ql;
    int idx = blockIdx.x * blockDim.x + threadIdx.x;
    int m   = idx >> 10;
    int rem = idx & 1023;
    int h   = rem >> 6;
    int j   = rem & 63;
    int s   = m & (SEQ - 1);
    float freq = exp2f(-(float)j * 0.20762050593045951f);
    float ang  = (float)s * freq;
    float sn, cs;
    sincosf(ang, &sn, &cs);
    size_t base = (size_t)m * DIM + h * HD + j;
    float t1 = src[base], t2 = src[base + 64];
    float r1 = t1 * cs - t2 * sn;
    float r2 = t2 * cs + t1 * sn;
    if (!which) { r1 *= 0.088388347648318447f; r2 *= 0.088388347648318447f; }
    __nv_bfloat16 h1 = __float2bfloat16(r1);
    __nv_bfloat16 h2 = __float2bfloat16(r2);
    oh[base]      = h1;
    oh[base + 64] = h2;
    ol[base]      = __float2bfloat16(r1 - __bfloat162float(h1));
    ol[base + 64] = __float2bfloat16(r2 - __bfloat162float(h2));
}

// ---------------- V transpose + split: g_v[b,s][h,d] -> g_vt[bh][d][s] ----------------
__global__ void vt_split_kernel()
{
    __shared__ float tile[32][33];
    const int bh = blockIdx.z;
    const int b  = bh >> 4, h = bh & 15;
    const int s0 = blockIdx.x * 32;
    const int d0 = blockIdx.y * 32;
    const int tx = threadIdx.x, ty = threadIdx.y;

    #pragma unroll
    for (int i = 0; i < 4; ++i) {
        int s = s0 + ty + 8*i;
        tile[ty + 8*i][tx] = g_v[(size_t)(b*SEQ + s)*DIM + h*HD + d0 + tx];
    }
    __syncthreads();
    #pragma unroll
    for (int i = 0; i < 4; ++i) {
        int d = d0 + ty + 8*i;
        float v = tile[tx][ty + 8*i];
        __nv_bfloat16 hh = __float2bfloat16(v);
        size_t o = ((size_t)bh*HD + d)*SEQ + s0 + tx;
        g_vth[o] = hh;
        g_vtl[o] = __float2bfloat16(v - __bfloat162float(hh));
    }
}

// ---------------- flash attention on mma.sync ----------------
// BM=BN=128, Hd=128, 8 warps; warp owns 16 rows x 128 cols.
__global__ __launch_bounds__(256, 1) void flash_mma_kernel()
{
    extern __shared__ __nv_bfloat16 sh[];
    const uint32_t su = smem_u32(sh);
    const uint32_t sQh = su;
    const uint32_t sQl = su + FT_B;
    const uint32_t sKh = su + 2*FT_B;
    const uint32_t sKl = su + 3*FT_B;
    const uint32_t sVh = su + 4*FT_B;
    const uint32_t sVl = su + 5*FT_B;

    const int t    = threadIdx.x;
    const int wid  = t >> 5;
    const int lane = t & 31;
    const int g    = lane >> 2;
    const int tg   = lane & 3;

    const int qt = (int)gridDim.x - 1 - (int)blockIdx.x;
    const int bh = blockIdx.y;
    const int b  = bh >> 4, h = bh & 15;
    const size_t row_base = (size_t)(b * SEQ + qt * 128);

    // ldmatrix per-lane address parts (elements)
    const int a_r = (lane & 15);
    const int a_c = (lane >> 4) << 3;
    const int b_r = ((lane >> 4) << 3) + (lane & 7);
    const int b_c = ((lane >> 3) & 1) << 3;

    // load Q (hi/lo)
    {
        const __nv_bfloat16* Qgh = g_qh + row_base * DIM + h * HD;
        const __nv_bfloat16* Qgl = g_ql + row_base * DIM + h * HD;
        #pragma unroll
        for (int it = 0; it < 8; ++it) {
            int s = t + 256*it; int r = s >> 4, c = (s & 15) * 8;
            *(uint4*)(sh + r*SR + c)        = *(const uint4*)(Qgh + (size_t)r*DIM + c);
            *(uint4*)(sh + FT_E + r*SR + c) = *(const uint4*)(Qgl + (size_t)r*DIM + c);
        }
    }

    float s_[16][4];
    float o_[16][4];
    float m_a = -1e30f, m_b = -1e30f, l_a = 0.f, l_b = 0.f;
    #pragma unroll
    for (int nt = 0; nt < 16; ++nt)
        #pragma unroll
        for (int r = 0; r < 4; ++r) o_[nt][r] = 0.f;

    __syncthreads();

    for (int jt = 0; jt <= qt; ++jt) {
        // load K and Vt tiles (hi/lo)
        {
            const size_t krow = (size_t)(b * SEQ + jt * 128);
            const __nv_bfloat16* Kgh = g_kh + krow * DIM + h * HD;
            const __nv_bfloat16* Kgl = g_kl + krow * DIM + h * HD;
            const __nv_bfloat16* Vgh = g_vth + (size_t)bh * HD * SEQ + jt * 128;
            const __nv_bfloat16* Vgl = g_vtl + (size_t)bh * HD * SEQ + jt * 128;
            #pragma unroll
            for (int it = 0; it < 8; ++it) {
                int s = t + 256*it; int r = s >> 4, c = (s & 15) * 8;
                *(uint4*)(sh + 2*FT_E + r*SR + c) = *(const uint4*)(Kgh + (size_t)r*DIM + c);
                *(uint4*)(sh + 3*FT_E + r*SR + c) = *(const uint4*)(Kgl + (size_t)r*DIM + c);
                *(uint4*)(sh + 4*FT_E + r*SR + c) = *(const uint4*)(Vgh + (size_t)r*SEQ + c);
                *(uint4*)(sh + 5*FT_E + r*SR + c) = *(const uint4*)(Vgl + (size_t)r*SEQ + c);
            }
        }
        __syncthreads();

        // S = Q K^T  (16 x 128 per warp)
        #pragma unroll
        for (int nt = 0; nt < 16; ++nt)
            #pragma unroll
            for (int r = 0; r < 4; ++r) s_[nt][r] = 0.f;

        #pragma unroll
        for (int ks = 0; ks < 8; ++ks) {
            uint32_t aH[4], aL[4];
            uint32_t offA = 2*((wid*16 + a_r)*SR + ks*16 + a_c);
            LDSM4(aH[0], aH[1], aH[2], aH[3], sQh + offA);
            LDSM4(aL[0], aL[1], aL[2], aL[3], sQl + offA);
            #pragma unroll
            for (int np = 0; np < 8; ++np) {
                uint32_t bH[4], bL[4];
                uint32_t offB = 2*((np*16 + b_r)*SR + ks*16 + b_c);
                LDSM4(bH[0], bH[1], bH[2], bH[3], sKh + offB);
                LDSM4(bL[0], bL[1], bL[2], bL[3], sKl + offB);
                mma16816(s_[2*np],   aH, &bH[0]);
                mma16816(s_[2*np],   aH, &bL[0]);
                mma16816(s_[2*np],   aL, &bH[0]);
                mma16816(s_[2*np+1], aH, &bH[2]);
                mma16816(s_[2*np+1], aH, &bL[2]);
                mma16816(s_[2*np+1], aL, &bH[2]);
            }
        }

        // causal mask on diagonal tile
        if (jt == qt) {
            const int ra = wid*16 + g, rb2 = ra + 8;
            #pragma unroll
            for (int nt = 0; nt < 16; ++nt) {
                int c0 = nt*8 + 2*tg;
                if (c0     > ra)  s_[nt][0] = -1e30f;
                if (c0 + 1 > ra)  s_[nt][1] = -1e30f;
                if (c0     > rb2) s_[nt][2] = -1e30f;
                if (c0 + 1 > rb2) s_[nt][3] = -1e30f;
            }
        }

        // online softmax (rows g and g+8 of warp tile)
        {
            float mxa = -1e30f, mxb = -1e30f;
            #pragma unroll
            for (int nt = 0; nt < 16; ++nt) {
                mxa = fmaxf(mxa, fmaxf(s_[nt][0], s_[nt][1]));
                mxb = fmaxf(mxb, fmaxf(s_[nt][2], s_[nt][3]));
            }
            #pragma unroll
            for (int w = 1; w < 4; w <<= 1) {
                mxa = fmaxf(mxa, __shfl_xor_sync(0xffffffffu, mxa, w));
                mxb = fmaxf(mxb, __shfl_xor_sync(0xffffffffu, mxb, w));
            }
            float mna = fmaxf(m_a, mxa), mnb = fmaxf(m_b, mxb);
            float ca = __expf(m_a - mna), cb = __expf(m_b - mnb);
            m_a = mna; m_b = mnb;
            float sa = 0.f, sb = 0.f;
            #pragma unroll
            for (int nt = 0; nt < 16; ++nt) {
                s_[nt][0] = __expf(s_[nt][0] - mna);
                s_[nt][1] = __expf(s_[nt][1] - mna);
                s_[nt][2] = __expf(s_[nt][2] - mnb);
                s_[nt][3] = __expf(s_[nt][3] - mnb);
                sa += s_[nt][0] + s_[nt][1];
                sb += s_[nt][2] + s_[nt][3];
            }
            #pragma unroll
            for (int w = 1; w < 4; w <<= 1) {
                sa += __shfl_xor_sync(0xffffffffu, sa, w);
                sb += __shfl_xor_sync(0xffffffffu, sb, w);
            }
            l_a = l_a * ca + sa;
            l_b = l_b * cb + sb;
            #pragma unroll
            for (int nt = 0; nt < 16; ++nt) {
                o_[nt][0] *= ca; o_[nt][1] *= ca;
                o_[nt][2] *= cb; o_[nt][3] *= cb;
            }
        }

        // O += P V   (A frags from s_ registers; B from Vt smem)
        #pragma unroll
        for (int kk = 0; kk < 8; ++kk) {
            uint32_t aPh[4], aPl[4];
            split2(s_[2*kk][0],   s_[2*kk][1],   aPh[0], aPl[0]);
            split2(s_[2*kk][2],   s_[2*kk][3],   aPh[1], aPl[1]);
            split2(s_[2*kk+1][0], s_[2*kk+1][1], aPh[2], aPl[2]);
            split2(s_[2*kk+1][2], s_[2*kk+1][3], aPh[3], aPl[3]);
            #pragma unroll
            for (int np = 0; np < 8; ++np) {
                uint32_t bH[4], bL[4];
                uint32_t offB = 2*((np*16 + b_r)*SR + kk*16 + b_c);
                LDSM4(bH[0], bH[1], bH[2], bH[3], sVh + offB);
                LDSM4(bL[0], bL[1], bL[2], bL[3], sVl + offB);
                mma16816(o_[2*np],   aPh, &bH[0]);
                mma16816(o_[2*np],   aPh, &bL[0]);
                mma16816(o_[2*np],   aPl, &bH[0]);
                mma16816(o_[2*np+1], aPh, &bH[2]);
                mma16816(o_[2*np+1], aPh, &bL[2]);
                mma16816(o_[2*np+1], aPl, &bH[2]);
            }
        }
        __syncthreads();   // K/V consumed before next overwrite
    }

    // epilogue: O /= l, write bf16 hi/lo split
    {
        float ia = 1.f / l_a, ib = 1.f / l_b;
        const int ra = wid*16 + g;
        __nv_bfloat16* Oh = g_aoh + row_base * DIM + h * HD;
        __nv_bfloat16* Ol = g_aol + row_base * DIM + h * HD;
        #pragma unroll
        for (int nt = 0; nt < 16; ++nt) {
            int c = nt*8 + 2*tg;
            uint32_t ph, pl;
            split2(o_[nt][0]*ia, o_[nt][1]*ia, ph, pl);
            *(uint32_t*)(Oh + (size_t)ra*DIM + c) = ph;
            *(uint32_t*)(Ol + (size_t)ra*DIM + c) = pl;
            split2(o_[nt][2]*ib, o_[nt][3]*ib, ph, pl);
            *(uint32_t*)(Oh + (size_t)(ra+8)*DIM + c) = ph;
            *(uint32_t*)(Ol + (size_t)(ra+8)*DIM + c) = pl;
        }
    }
}

// ---------------------------------------------------------------------------
extern "C" void kernel_launch(void* const* d_in, const int* in_sizes, int n_in,
                              void* d_out, int out_size)
{
    const float* x  = (const float*)d_in[0];
    const float* Wq = (const float*)d_in[1];
    const float* Wk = (const float*)d_in[2];
    const float* Wv = (const float*)d_in[3];
    const float* Wo = (const float*)d_in[4];
    const float* bo = (const float*)d_in[5];
    float* out = (float*)d_out;

    cudaFuncSetAttribute(flash_mma_kernel,
        cudaFuncAttributeMaxDynamicSharedMemorySize, FLASH_SMEM);
    cudaFuncSetAttribute(qkv_mma_kernel,
        cudaFuncAttributeMaxDynamicSharedMemorySize, GEMM_SMEM);
    cudaFuncSetAttribute(out_mma_kernel,
        cudaFuncAttributeMaxDynamicSharedMemorySize, GEMM_SMEM);

    // bf16 hi/lo splits of inputs
    split_bf16_kernel<<<(MROWS*DIM/4)/256, 256>>>(x,  0, MROWS*DIM/4);
    split_bf16_kernel<<<(DD/4)/256, 256>>>(Wq, 1, DD/4);
    split_bf16_kernel<<<(DD/4)/256, 256>>>(Wk, 2, DD/4);
    split_bf16_kernel<<<(DD/4)/256, 256>>>(Wv, 3, DD/4);
    split_bf16_kernel<<<(DD/4)/256, 256>>>(Wo, 4, DD/4);

    // QKV projections
    dim3 gq(DIM/128, MROWS/128, 3);
    qkv_mma_kernel<<<gq, 256, GEMM_SMEM>>>();

    // RoPE + split (q scaled), V transpose + split
    int rope_blocks = (MROWS * 1024) / 256;
    rope_split_kernel<<<rope_blocks, 256>>>(0);
    rope_split_kernel<<<rope_blocks, 256>>>(1);
    vt_split_kernel<<<dim3(SEQ/32, HD/32, BATCH*NHEADS), dim3(32, 8)>>>();

    // flash attention on tensor cores
    dim3 gf(SEQ/128, BATCH*NHEADS);
    flash_mma_kernel<<<gf, 256, FLASH_SMEM>>>();

    // output projection
    dim3 go(DIM/128, MROWS/128);
    out_mma_kernel<<<go, 256, GEMM_SMEM>>>(out, bo);
}

// round 5
// speedup vs baseline: 2.7950x; 1.0204x over previous
#include <cuda_runtime.h>
#include <cuda_bf16.h>
#include <math.h>
#include <stdint.h>

#define DIM 2048
#define NHEADS 16
#define HD 128
#define BATCH 4
#define SEQ 2048
#define MROWS (BATCH*SEQ)   // 8192
#define DD (DIM*DIM)

// GEMM tiling
#define KT 32               // bf16 K per smem stage
#define NKI (DIM/KT)        // 64 k-iterations
#define AROW 40             // smem row: 32 bf16 + 8 pad (80 B)
#define TILE_E (128*AROW)
#define TILE_BYTES (TILE_E*2)          // 10240
#define STAGE_B (4*TILE_BYTES)         // 40960 (Ah,Al,Bh,Bl)
#define NSTAGE 4
#define GEMM_SMEM (NSTAGE*STAGE_B)     // 163840

// flash smem
#define SR 136                          // 128 + 8 pad bf16
#define FT_E (128*SR)
#define FT_B (FT_E*2)                   // 34816 bytes
#define FLASH_SMEM (6*FT_B)             // 208896

// ---------------- scratch (static device memory) ----------------
__device__ float g_q [MROWS*DIM];
__device__ float g_k [MROWS*DIM];
__device__ float g_v [MROWS*DIM];
__device__ __nv_bfloat16 g_xh[MROWS*DIM];
__device__ __nv_bfloat16 g_xl[MROWS*DIM];
__device__ __nv_bfloat16 g_wh[4*DD];
__device__ __nv_bfloat16 g_wl[4*DD];
__device__ __nv_bfloat16 g_aoh[MROWS*DIM];
__device__ __nv_bfloat16 g_aol[MROWS*DIM];
__device__ __nv_bfloat16 g_qh[MROWS*DIM];
__device__ __nv_bfloat16 g_ql[MROWS*DIM];
__device__ __nv_bfloat16 g_kh[MROWS*DIM];
__device__ __nv_bfloat16 g_kl[MROWS*DIM];
__device__ __nv_bfloat16 g_vth[MROWS*DIM];   // [bh][d][s]
__device__ __nv_bfloat16 g_vtl[MROWS*DIM];

// ---------------- helpers ----------------
__device__ __forceinline__ uint32_t smem_u32(const void* p) {
    uint32_t a;
    asm("{ .reg .u64 t; cvta.to.shared.u64 t, %1; cvt.u32.u64 %0, t; }" : "=r"(a) : "l"(p));
    return a;
}
#define LDSM4(r0,r1,r2,r3,addr) \
    asm volatile("ldmatrix.sync.aligned.m8n8.x4.shared.b16 {%0,%1,%2,%3}, [%4];" \
        : "=r"(r0), "=r"(r1), "=r"(r2), "=r"(r3) : "r"(addr))
#define CP_ASYNC16(sa, ga) \
    asm volatile("cp.async.cg.shared.global [%0], [%1], 16;" :: "r"(sa), "l"(ga))
#define CP_COMMIT() asm volatile("cp.async.commit_group;" ::: "memory")
#define CP_WAIT(n)  asm volatile("cp.async.wait_group %0;" :: "n"(n) : "memory")

__device__ __forceinline__ void mma16816(float* d, const uint32_t* a, const uint32_t* b)
{
    asm volatile(
        "mma.sync.aligned.m16n8k16.row.col.f32.bf16.bf16.f32 "
        "{%0,%1,%2,%3}, {%4,%5,%6,%7}, {%8,%9}, {%0,%1,%2,%3};"
        : "+f"(d[0]), "+f"(d[1]), "+f"(d[2]), "+f"(d[3])
        : "r"(a[0]), "r"(a[1]), "r"(a[2]), "r"(a[3]), "r"(b[0]), "r"(b[1]));
}

__device__ __forceinline__ void split2(float x, float y, uint32_t& h, uint32_t& l) {
    __nv_bfloat16 hx = __float2bfloat16(x), hy = __float2bfloat16(y);
    __nv_bfloat162 hp(hx, hy);
    h = *(uint32_t*)&hp;
    __nv_bfloat162 lp(__float2bfloat16(x - __bfloat162float(hx)),
                      __float2bfloat16(y - __bfloat162float(hy)));
    l = *(uint32_t*)&lp;
}

// ---------------- bf16 hi/lo split (x and weights) ----------------
__global__ void split_bf16_kernel(const float* __restrict__ in, int sel, int n4)
{
    int i = blockIdx.x * blockDim.x + threadIdx.x;
    if (i >= n4) return;
    __nv_bfloat16 *oh, *ol;
    if (sel == 0) { oh = g_xh; ol = g_xl; }
    else { size_t off = (size_t)(sel - 1) * DD; oh = g_wh + off; ol = g_wl + off; }
    float4 v = ((const float4*)in)[i];
    __nv_bfloat16 h0 = __float2bfloat16(v.x);
    __nv_bfloat16 h1 = __float2bfloat16(v.y);
    __nv_bfloat16 h2 = __float2bfloat16(v.z);
    __nv_bfloat16 h3 = __float2bfloat16(v.w);
    __nv_bfloat162* ohp = (__nv_bfloat162*)oh;
    __nv_bfloat162* olp = (__nv_bfloat162*)ol;
    ohp[i*2+0] = __nv_bfloat162(h0, h1);
    ohp[i*2+1] = __nv_bfloat162(h2, h3);
    olp[i*2+0] = __nv_bfloat162(__float2bfloat16(v.x - __bfloat162float(h0)),
                                __float2bfloat16(v.y - __bfloat162float(h1)));
    olp[i*2+1] = __nv_bfloat162(__float2bfloat16(v.z - __bfloat162float(h2)),
                                __float2bfloat16(v.w - __bfloat162float(h3)));
}

// ---------------- pipelined split-bf16 NT GEMM on mma.sync ----------------
__device__ __forceinline__ void gemm_issue_stage(
    uint32_t su, int slot, int kt,
    const __nv_bfloat16* s0, const __nv_bfloat16* s1,
    const __nv_bfloat16* s2, const __nv_bfloat16* s3,
    int rbA, int rbB, int t)
{
    const int ko = kt * KT;
    const uint32_t base = su + slot * STAGE_B;
    const __nv_bfloat16* srcs[4] = { s0, s1, s2, s3 };
    const int rb[4] = { rbA, rbA, rbB, rbB };
    #pragma unroll
    for (int q = 0; q < 4; ++q)
        #pragma unroll
        for (int i = 0; i < 2; ++i) {
            int s = t + 256*i; int r = s >> 2, v = s & 3;
            uint32_t sa = base + q*TILE_BYTES + r*80 + v*16;
            const void* ga = srcs[q] + (size_t)(rb[q]+r)*DIM + ko + v*8;
            CP_ASYNC16(sa, ga);
        }
}

__device__ __forceinline__ void gemm_mma_body(
    const __nv_bfloat16* __restrict__ Ah, const __nv_bfloat16* __restrict__ Al,
    const __nv_bfloat16* __restrict__ Bh, const __nv_bfloat16* __restrict__ Bl,
    float* __restrict__ C, const float* __restrict__ bias, int bn, int bm)
{
    extern __shared__ __nv_bfloat16 sm[];
    const uint32_t su = smem_u32(sm);
    const int t    = threadIdx.x;
    const int wid  = t >> 5;
    const int lane = t & 31;
    const int g    = lane >> 2;
    const int tg   = lane & 3;
    const int mo   = (wid & 1) * 64;
    const int no   = (wid >> 1) * 32;
    const int rbA  = bm * 128, rbB = bn * 128;

    const int a_r = (lane & 15);
    const int a_c = (lane >> 4) << 3;
    const int b_r = ((lane >> 4) << 3) + (lane & 7);
    const int b_c = ((lane >> 3) & 1) << 3;

    float acc[4][4][4];
    #pragma unroll
    for (int mt = 0; mt < 4; ++mt)
        #pragma unroll
        for (int nt = 0; nt < 4; ++nt)
            #pragma unroll
            for (int r = 0; r < 4; ++r) acc[mt][nt][r] = 0.f;

    // prologue: 3 stages in flight
    #pragma unroll
    for (int st = 0; st < 3; ++st) {
        gemm_issue_stage(su, st, st, Ah, Al, Bh, Bl, rbA, rbB, t);
        CP_COMMIT();
    }

    for (int kt = 0; kt < NKI; ++kt) {
        CP_WAIT(2);
        __syncthreads();
        if (kt + 3 < NKI)
            gemm_issue_stage(su, (kt+3) & 3, kt+3, Ah, Al, Bh, Bl, rbA, rbB, t);
        CP_COMMIT();

        const uint32_t buf = su + (kt & 3) * STAGE_B;
        const uint32_t tAh = buf;
        const uint32_t tAl = buf + TILE_BYTES;
        const uint32_t tBh = buf + 2*TILE_BYTES;
        const uint32_t tBl = buf + 3*TILE_BYTES;

        #pragma unroll
        for (int ks = 0; ks < 2; ++ks) {
            uint32_t aH[4][4], aL[4][4], bH[2][4], bL[2][4];
            #pragma unroll
            for (int mt = 0; mt < 4; ++mt) {
                uint32_t off = 2*((mo + mt*16 + a_r)*AROW + ks*16 + a_c);
                LDSM4(aH[mt][0], aH[mt][1], aH[mt][2], aH[mt][3], tAh + off);
                LDSM4(aL[mt][0], aL[mt][1], aL[mt][2], aL[mt][3], tAl + off);
            }
            #pragma unroll
            for (int np = 0; np < 2; ++np) {
                uint32_t off = 2*((no + np*16 + b_r)*AROW + ks*16 + b_c);
                LDSM4(bH[np][0], bH[np][1], bH[np][2], bH[np][3], tBh + off);
                LDSM4(bL[np][0], bL[np][1], bL[np][2], bL[np][3], tBl + off);
            }
            #pragma unroll
            for (int mt = 0; mt < 4; ++mt)
                #pragma unroll
                for (int np = 0; np < 2; ++np) {
                    mma16816(acc[mt][2*np],   aH[mt], &bH[np][0]);
                    mma16816(acc[mt][2*np],   aH[mt], &bL[np][0]);
                    mma16816(acc[mt][2*np],   aL[mt], &bH[np][0]);
                    mma16816(acc[mt][2*np+1], aH[mt], &bH[np][2]);
                    mma16816(acc[mt][2*np+1], aH[mt], &bL[np][2]);
                    mma16816(acc[mt][2*np+1], aL[mt], &bH[np][2]);
                }
        }
    }

    const int row0 = bm*128, col0 = bn*128;
    #pragma unroll
    for (int mt = 0; mt < 4; ++mt) {
        int r = row0 + mo + mt*16 + g;
        #pragma unroll
        for (int nt = 0; nt < 4; ++nt) {
            int c = col0 + no + nt*8 + 2*tg;
            float b0 = 0.f, b1 = 0.f;
            if (bias) { b0 = bias[c]; b1 = bias[c+1]; }
            float2 v0 = make_float2(acc[mt][nt][0] + b0, acc[mt][nt][1] + b1);
            float2 v1 = make_float2(acc[mt][nt][2] + b0, acc[mt][nt][3] + b1);
            *(float2*)&C[(size_t)r * DIM + c]     = v0;
            *(float2*)&C[(size_t)(r+8) * DIM + c] = v1;
        }
    }
}

__global__ __launch_bounds__(256, 1) void qkv_mma_kernel()
{
    const int z = blockIdx.z;
    float* C = (z == 0) ? g_q : (z == 1 ? g_k : g_v);
    gemm_mma_body(g_xh, g_xl, g_wh + (size_t)z*DD, g_wl + (size_t)z*DD,
                  C, nullptr, blockIdx.x, blockIdx.y);
}

__global__ __launch_bounds__(256, 1) void out_mma_kernel(
    float* __restrict__ out, const float* __restrict__ bo)
{
    gemm_mma_body(g_aoh, g_aol, g_wh + (size_t)3*DD, g_wl + (size_t)3*DD,
                  out, bo, blockIdx.x, blockIdx.y);
}

// ---------------- RoPE + bf16 split (q: scaled) ----------------
__global__ void rope_split_kernel(int which)
{
    const float* src = which ? g_k : g_q;
    __nv_bfloat16* oh = which ? g_kh : g_qh;
    __nv_bfloat16* ol = which ? g_kl : g_ql;
    int idx = blockIdx.x * blockDim.x + threadIdx.x;
    int m   = idx >> 10;
    int rem = idx & 1023;
    int h   = rem >> 6;
    int j   = rem & 63;
    int s   = m & (SEQ - 1);
    float freq = exp2f(-(float)j * 0.20762050593045951f);
    float ang  = (float)s * freq;
    float sn, cs;
    sincosf(ang, &sn, &cs);
    size_t base = (size_t)m * DIM + h * HD + j;
    float t1 = src[base], t2 = src[base + 64];
    float r1 = t1 * cs - t2 * sn;
    float r2 = t2 * cs + t1 * sn;
    if (!which) { r1 *= 0.088388347648318447f; r2 *= 0.088388347648318447f; }
    __nv_bfloat16 h1 = __float2bfloat16(r1);
    __nv_bfloat16 h2 = __float2bfloat16(r2);
    oh[base]      = h1;
    oh[base + 64] = h2;
    ol[base]      = __float2bfloat16(r1 - __bfloat162float(h1));
    ol[base + 64] = __float2bfloat16(r2 - __bfloat162float(h2));
}

// ---------------- V transpose + split ----------------
__global__ void vt_split_kernel()
{
    __shared__ float tile[32][33];
    const int bh = blockIdx.z;
    const int b  = bh >> 4, h = bh & 15;
    const int s0 = blockIdx.x * 32;
    const int d0 = blockIdx.y * 32;
    const int tx = threadIdx.x, ty = threadIdx.y;

    #pragma unroll
    for (int i = 0; i < 4; ++i) {
        int s = s0 + ty + 8*i;
        tile[ty + 8*i][tx] = g_v[(size_t)(b*SEQ + s)*DIM + h*HD + d0 + tx];
    }
    __syncthreads();
    #pragma unroll
    for (int i = 0; i < 4; ++i) {
        int d = d0 + ty + 8*i;
        float v = tile[tx][ty + 8*i];
        __nv_bfloat16 hh = __float2bfloat16(v);
        size_t o = ((size_t)bh*HD + d)*SEQ + s0 + tx;
        g_vth[o] = hh;
        g_vtl[o] = __float2bfloat16(v - __bfloat162float(hh));
    }
}

// ---------------- pipelined flash attention on mma.sync ----------------
// Regions: RA = tiles 0,1 (Q prologue, then K ping buf 1); RB = tiles 2,3 (K buf 0);
// V = tiles 4,5. Q lives in registers after prologue.
__device__ __forceinline__ void flash_issue_pair(
    uint32_t dh, uint32_t dl,
    const __nv_bfloat16* gh, const __nv_bfloat16* gl, int stride, int t)
{
    #pragma unroll
    for (int i = 0; i < 8; ++i) {
        int s = t + 256*i; int r = s >> 4; int c16 = (s & 15) * 16;
        CP_ASYNC16(dh + r*272 + c16, (const char*)gh + (size_t)r*stride*2 + c16);
        CP_ASYNC16(dl + r*272 + c16, (const char*)gl + (size_t)r*stride*2 + c16);
    }
}

__global__ __launch_bounds__(256, 1) void flash_mma_kernel()
{
    extern __shared__ __nv_bfloat16 sh[];
    const uint32_t su = smem_u32(sh);
    const uint32_t RA = su;
    const uint32_t RB = su + 2*FT_B;
    const uint32_t sV = su + 4*FT_B;

    const int t    = threadIdx.x;
    const int wid  = t >> 5;
    const int lane = t & 31;
    const int g    = lane >> 2;
    const int tg   = lane & 3;

    const int qt = (int)gridDim.x - 1 - (int)blockIdx.x;
    const int bh = blockIdx.y;
    const int b  = bh >> 4, h = bh & 15;
    const size_t row_base = (size_t)(b * SEQ + qt * 128);

    const int a_r = (lane & 15);
    const int a_c = (lane >> 4) << 3;
    const int b_r = ((lane >> 4) << 3) + (lane & 7);
    const int b_c = ((lane >> 3) & 1) << 3;

    const __nv_bfloat16* Kh0 = g_kh + (size_t)b*SEQ*DIM + h*HD;
    const __nv_bfloat16* Kl0 = g_kl + (size_t)b*SEQ*DIM + h*HD;
    const __nv_bfloat16* Vh0 = g_vth + (size_t)bh*HD*SEQ;
    const __nv_bfloat16* Vl0 = g_vtl + (size_t)bh*HD*SEQ;

    // prologue: Q -> RA, K(0) -> RB, V(0) -> sV
    flash_issue_pair(RA, RA + FT_B,
                     g_qh + row_base*DIM + h*HD, g_ql + row_base*DIM + h*HD, DIM, t);
    CP_COMMIT();
    flash_issue_pair(RB, RB + FT_B, Kh0, Kl0, DIM, t);
    CP_COMMIT();
    flash_issue_pair(sV, sV + FT_B, Vh0, Vl0, SEQ, t);
    CP_COMMIT();
    CP_WAIT(0);
    __syncthreads();

    // Q fragments into registers
    uint32_t qH[8][4], qL[8][4];
    #pragma unroll
    for (int ks = 0; ks < 8; ++ks) {
        uint32_t off = 2*((wid*16 + a_r)*SR + ks*16 + a_c);
        LDSM4(qH[ks][0], qH[ks][1], qH[ks][2], qH[ks][3], RA + off);
        LDSM4(qL[ks][0], qL[ks][1], qL[ks][2], qL[ks][3], RA + FT_B + off);
    }
    __syncthreads();   // RA may now be reused as K buffer

    float s_[16][4];
    float o_[16][4];
    float m_a = -1e30f, m_b = -1e30f, l_a = 0.f, l_b = 0.f;
    #pragma unroll
    for (int nt = 0; nt < 16; ++nt)
        #pragma unroll
        for (int r = 0; r < 4; ++r) o_[nt][r] = 0.f;

    for (int jt = 0; jt <= qt; ++jt) {
        // prefetch next K into the other K buffer (spans entire S phase)
        if (jt < qt) {
            uint32_t kb = ((jt+1) & 1) ? RA : RB;
            flash_issue_pair(kb, kb + FT_B,
                             Kh0 + (size_t)(jt+1)*128*DIM, Kl0 + (size_t)(jt+1)*128*DIM,
                             DIM, t);
        }
        CP_COMMIT();

        const uint32_t sKh = (jt & 1) ? RA : RB;
        const uint32_t sKl = sKh + FT_B;

        // S = Q K^T
        #pragma unroll
        for (int nt = 0; nt < 16; ++nt)
            #pragma unroll
            for (int r = 0; r < 4; ++r) s_[nt][r] = 0.f;

        #pragma unroll
        for (int ks = 0; ks < 8; ++ks) {
            #pragma unroll
            for (int np = 0; np < 8; ++np) {
                uint32_t bH[4], bL[4];
                uint32_t offB = 2*((np*16 + b_r)*SR + ks*16 + b_c);
                LDSM4(bH[0], bH[1], bH[2], bH[3], sKh + offB);
                LDSM4(bL[0], bL[1], bL[2], bL[3], sKl + offB);
                mma16816(s_[2*np],   qH[ks], &bH[0]);
                mma16816(s_[2*np],   qH[ks], &bL[0]);
                mma16816(s_[2*np],   qL[ks], &bH[0]);
                mma16816(s_[2*np+1], qH[ks], &bH[2]);
                mma16816(s_[2*np+1], qH[ks], &bL[2]);
                mma16816(s_[2*np+1], qL[ks], &bH[2]);
            }
        }

        if (jt == qt) {
            const int ra = wid*16 + g, rb2 = ra + 8;
            #pragma unroll
            for (int nt = 0; nt < 16; ++nt) {
                int c0 = nt*8 + 2*tg;
                if (c0     > ra)  s_[nt][0] = -1e30f;
                if (c0 + 1 > ra)  s_[nt][1] = -1e30f;
                if (c0     > rb2) s_[nt][2] = -1e30f;
                if (c0 + 1 > rb2) s_[nt][3] = -1e30f;
            }
        }

        // online softmax
        {
            float mxa = -1e30f, mxb = -1e30f;
            #pragma unroll
            for (int nt = 0; nt < 16; ++nt) {
                mxa = fmaxf(mxa, fmaxf(s_[nt][0], s_[nt][1]));
                mxb = fmaxf(mxb, fmaxf(s_[nt][2], s_[nt][3]));
            }
            #pragma unroll
            for (int w = 1; w < 4; w <<= 1) {
                mxa = fmaxf(mxa, __shfl_xor_sync(0xffffffffu, mxa, w));
                mxb = fmaxf(mxb, __shfl_xor_sync(0xffffffffu, mxb, w));
            }
            float mna = fmaxf(m_a, mxa), mnb = fmaxf(m_b, mxb);
            float ca = __expf(m_a - mna), cb = __expf(m_b - mnb);
            m_a = mna; m_b = mnb;
            float sa = 0.f, sb = 0.f;
            #pragma unroll
            for (int nt = 0; nt < 16; ++nt) {
                s_[nt][0] = __expf(s_[nt][0] - mna);
                s_[nt][1] = __expf(s_[nt][1] - mna);
                s_[nt][2] = __expf(s_[nt][2] - mnb);
                s_[nt][3] = __expf(s_[nt][3] - mnb);
                sa += s_[nt][0] + s_[nt][1];
                sb += s_[nt][2] + s_[nt][3];
            }
            #pragma unroll
            for (int w = 1; w < 4; w <<= 1) {
                sa += __shfl_xor_sync(0xffffffffu, sa, w);
                sb += __shfl_xor_sync(0xffffffffu, sb, w);
            }
            l_a = l_a * ca + sa;
            l_b = l_b * cb + sb;
            #pragma unroll
            for (int nt = 0; nt < 16; ++nt) {
                o_[nt][0] *= ca; o_[nt][1] *= ca;
                o_[nt][2] *= cb; o_[nt][3] *= cb;
            }
        }

        CP_WAIT(1);         // V(jt) complete (oldest group); K(jt+1) may pend
        __syncthreads();

        // O += P V
        #pragma unroll
        for (int kk = 0; kk < 8; ++kk) {
            uint32_t aPh[4], aPl[4];
            split2(s_[2*kk][0],   s_[2*kk][1],   aPh[0], aPl[0]);
            split2(s_[2*kk][2],   s_[2*kk][3],   aPh[1], aPl[1]);
            split2(s_[2*kk+1][0], s_[2*kk+1][1], aPh[2], aPl[2]);
            split2(s_[2*kk+1][2], s_[2*kk+1][3], aPh[3], aPl[3]);
            #pragma unroll
            for (int np = 0; np < 8; ++np) {
                uint32_t bH[4], bL[4];
                uint32_t offB = 2*((np*16 + b_r)*SR + kk*16 + b_c);
                LDSM4(bH[0], bH[1], bH[2], bH[3], sV + offB);
                LDSM4(bL[0], bL[1], bL[2], bL[3], sV + FT_B + offB);
                mma16816(o_[2*np],   aPh, &bH[0]);
                mma16816(o_[2*np],   aPh, &bL[0]);
                mma16816(o_[2*np],   aPl, &bH[0]);
                mma16816(o_[2*np+1], aPh, &bH[2]);
                mma16816(o_[2*np+1], aPh, &bL[2]);
                mma16816(o_[2*np+1], aPl, &bH[2]);
            }
        }
        __syncthreads();    // all warps done reading V

        if (jt < qt)
            flash_issue_pair(sV, sV + FT_B,
                             Vh0 + (size_t)(jt+1)*128, Vl0 + (size_t)(jt+1)*128, SEQ, t);
        CP_COMMIT();
        CP_WAIT(1);         // K(jt+1) complete; V(jt+1) may pend
        __syncthreads();
    }

    // epilogue
    {
        float ia = 1.f / l_a, ib = 1.f / l_b;
        const int ra = wid*16 + g;
        __nv_bfloat16* Oh = g_aoh + row_base * DIM + h * HD;
        __nv_bfloat16* Ol = g_aol + row_base * DIM + h * HD;
        #pragma unroll
        for (int nt = 0; nt < 16; ++nt) {
            int c = nt*8 + 2*tg;
            uint32_t ph, pl;
            split2(o_[nt][0]*ia, o_[nt][1]*ia, ph, pl);
            *(uint32_t*)(Oh + (size_t)ra*DIM + c) = ph;
            *(uint32_t*)(Ol + (size_t)ra*DIM + c) = pl;
            split2(o_[nt][2]*ib, o_[nt][3]*ib, ph, pl);
            *(uint32_t*)(Oh + (size_t)(ra+8)*DIM + c) = ph;
            *(uint32_t*)(Ol + (size_t)(ra+8)*DIM + c) = pl;
        }
    }
}

// ---------------------------------------------------------------------------
extern "C" void kernel_launch(void* const* d_in, const int* in_sizes, int n_in,
                              void* d_out, int out_size)
{
    const float* x  = (const float*)d_in[0];
    const float* Wq = (const float*)d_in[1];
    const float* Wk = (const float*)d_in[2];
    const float* Wv = (const float*)d_in[3];
    const float* Wo = (const float*)d_in[4];
    const float* bo = (const float*)d_in[5];
    float* out = (float*)d_out;

    cudaFuncSetAttribute(flash_mma_kernel,
        cudaFuncAttributeMaxDynamicSharedMemorySize, FLASH_SMEM);
    cudaFuncSetAttribute(qkv_mma_kernel,
        cudaFuncAttributeMaxDynamicSharedMemorySize, GEMM_SMEM);
    cudaFuncSetAttribute(out_mma_kernel,
        cudaFuncAttributeMaxDynamicSharedMemorySize, GEMM_SMEM);

    split_bf16_kernel<<<(MROWS*DIM/4)/256, 256>>>(x,  0, MROWS*DIM/4);
    split_bf16_kernel<<<(DD/4)/256, 256>>>(Wq, 1, DD/4);
    split_bf16_kernel<<<(DD/4)/256, 256>>>(Wk, 2, DD/4);
    split_bf16_kernel<<<(DD/4)/256, 256>>>(Wv, 3, DD/4);
    split_bf16_kernel<<<(DD/4)/256, 256>>>(Wo, 4, DD/4);

    dim3 gq(DIM/128, MROWS/128, 3);
    qkv_mma_kernel<<<gq, 256, GEMM_SMEM>>>();

    int rope_blocks = (MROWS * 1024) / 256;
    rope_split_kernel<<<rope_blocks, 256>>>(0);
    rope_split_kernel<<<rope_blocks, 256>>>(1);
    vt_split_kernel<<<dim3(SEQ/32, HD/32, BATCH*NHEADS), dim3(32, 8)>>>();

    dim3 gf(SEQ/128, BATCH*NHEADS);
    flash_mma_kernel<<<gf, 256, FLASH_SMEM>>>();

    dim3 go(DIM/128, MROWS/128);
    out_mma_kernel<<<go, 256, GEMM_SMEM>>>(out, bo);
}

// round 6
// speedup vs baseline: 3.1564x; 1.1293x over previous
#include <cuda_runtime.h>
#include <cuda_bf16.h>
#include <cuda_fp16.h>
#include <math.h>
#include <stdint.h>

#define DIM 2048
#define NHEADS 16
#define HD 128
#define BATCH 4
#define SEQ 2048
#define MROWS (BATCH*SEQ)   // 8192
#define DD (DIM*DIM)

// GEMM tiling
#define KT 32               // bf16 K per smem stage
#define NKI (DIM/KT)        // 64 k-iterations
#define AROW 40             // smem row: 32 bf16 + 8 pad (80 B)
#define TILE_E (128*AROW)
#define TILE_BYTES (TILE_E*2)          // 10240
#define STAGE_B (4*TILE_BYTES)         // 40960 (Ah,Al,Bh,Bl)
#define GEMM_SMEM (4*STAGE_B)          // 163840

// flash smem (fp16, single precision term)
#define SR 136                          // 128 + 8 pad halves
#define FT_E (128*SR)
#define FT_B (FT_E*2)                   // 34816 bytes per tile
#define FLASH_SMEM (5*FT_B)             // 174080: Q, K0, K1, V0, V1

// ---------------- scratch (static device memory) ----------------
__device__ float g_q [MROWS*DIM];
__device__ float g_k [MROWS*DIM];
__device__ float g_v [MROWS*DIM];
__device__ __nv_bfloat16 g_xh[MROWS*DIM];
__device__ __nv_bfloat16 g_xl[MROWS*DIM];
__device__ __nv_bfloat16 g_wh[4*DD];
__device__ __nv_bfloat16 g_wl[4*DD];
__device__ __nv_bfloat16 g_aoh[MROWS*DIM];
__device__ __nv_bfloat16 g_aol[MROWS*DIM];
__device__ __half g_qf [MROWS*DIM];
__device__ __half g_kf [MROWS*DIM];
__device__ __half g_vtf[MROWS*DIM];   // [bh][d][s]

// ---------------- helpers ----------------
__device__ __forceinline__ uint32_t smem_u32(const void* p) {
    uint32_t a;
    asm("{ .reg .u64 t; cvta.to.shared.u64 t, %1; cvt.u32.u64 %0, t; }" : "=r"(a) : "l"(p));
    return a;
}
#define LDSM4(r0,r1,r2,r3,addr) \
    asm volatile("ldmatrix.sync.aligned.m8n8.x4.shared.b16 {%0,%1,%2,%3}, [%4];" \
        : "=r"(r0), "=r"(r1), "=r"(r2), "=r"(r3) : "r"(addr))
#define CP_ASYNC16(sa, ga) \
    asm volatile("cp.async.cg.shared.global [%0], [%1], 16;" :: "r"(sa), "l"(ga))
#define CP_COMMIT() asm volatile("cp.async.commit_group;" ::: "memory")
#define CP_WAIT(n)  asm volatile("cp.async.wait_group %0;" :: "n"(n) : "memory")

__device__ __forceinline__ void mma16816(float* d, const uint32_t* a, const uint32_t* b)
{
    asm volatile(
        "mma.sync.aligned.m16n8k16.row.col.f32.bf16.bf16.f32 "
        "{%0,%1,%2,%3}, {%4,%5,%6,%7}, {%8,%9}, {%0,%1,%2,%3};"
        : "+f"(d[0]), "+f"(d[1]), "+f"(d[2]), "+f"(d[3])
        : "r"(a[0]), "r"(a[1]), "r"(a[2]), "r"(a[3]), "r"(b[0]), "r"(b[1]));
}
__device__ __forceinline__ void mma16816h(float* d, const uint32_t* a, const uint32_t* b)
{
    asm volatile(
        "mma.sync.aligned.m16n8k16.row.col.f32.f16.f16.f32 "
        "{%0,%1,%2,%3}, {%4,%5,%6,%7}, {%8,%9}, {%0,%1,%2,%3};"
        : "+f"(d[0]), "+f"(d[1]), "+f"(d[2]), "+f"(d[3])
        : "r"(a[0]), "r"(a[1]), "r"(a[2]), "r"(a[3]), "r"(b[0]), "r"(b[1]));
}

__device__ __forceinline__ void split2(float x, float y, uint32_t& h, uint32_t& l) {
    __nv_bfloat16 hx = __float2bfloat16(x), hy = __float2bfloat16(y);
    __nv_bfloat162 hp(hx, hy);
    h = *(uint32_t*)&hp;
    __nv_bfloat162 lp(__float2bfloat16(x - __bfloat162float(hx)),
                      __float2bfloat16(y - __bfloat162float(hy)));
    l = *(uint32_t*)&lp;
}
__device__ __forceinline__ uint32_t packh(float x, float y) {
    __half2 h = __floats2half2_rn(x, y);
    return *(uint32_t*)&h;
}

// ---------------- bf16 hi/lo split (x and weights) ----------------
__global__ void split_bf16_kernel(const float* __restrict__ in, int sel, int n4)
{
    int i = blockIdx.x * blockDim.x + threadIdx.x;
    if (i >= n4) return;
    __nv_bfloat16 *oh, *ol;
    if (sel == 0) { oh = g_xh; ol = g_xl; }
    else { size_t off = (size_t)(sel - 1) * DD; oh = g_wh + off; ol = g_wl + off; }
    float4 v = ((const float4*)in)[i];
    __nv_bfloat16 h0 = __float2bfloat16(v.x);
    __nv_bfloat16 h1 = __float2bfloat16(v.y);
    __nv_bfloat16 h2 = __float2bfloat16(v.z);
    __nv_bfloat16 h3 = __float2bfloat16(v.w);
    __nv_bfloat162* ohp = (__nv_bfloat162*)oh;
    __nv_bfloat162* olp = (__nv_bfloat162*)ol;
    ohp[i*2+0] = __nv_bfloat162(h0, h1);
    ohp[i*2+1] = __nv_bfloat162(h2, h3);
    olp[i*2+0] = __nv_bfloat162(__float2bfloat16(v.x - __bfloat162float(h0)),
                                __float2bfloat16(v.y - __bfloat162float(h1)));
    olp[i*2+1] = __nv_bfloat162(__float2bfloat16(v.z - __bfloat162float(h2)),
                                __float2bfloat16(v.w - __bfloat162float(h3)));
}

// ---------------- pipelined split-bf16 NT GEMM on mma.sync ----------------
__device__ __forceinline__ void gemm_issue_stage(
    uint32_t su, int slot, int kt,
    const __nv_bfloat16* s0, const __nv_bfloat16* s1,
    const __nv_bfloat16* s2, const __nv_bfloat16* s3,
    int rbA, int rbB, int t)
{
    const int ko = kt * KT;
    const uint32_t base = su + slot * STAGE_B;
    const __nv_bfloat16* srcs[4] = { s0, s1, s2, s3 };
    const int rb[4] = { rbA, rbA, rbB, rbB };
    #pragma unroll
    for (int q = 0; q < 4; ++q)
        #pragma unroll
        for (int i = 0; i < 2; ++i) {
            int s = t + 256*i; int r = s >> 2, v = s & 3;
            uint32_t sa = base + q*TILE_BYTES + r*80 + v*16;
            const void* ga = srcs[q] + (size_t)(rb[q]+r)*DIM + ko + v*8;
            CP_ASYNC16(sa, ga);
        }
}

__device__ __forceinline__ void gemm_mma_body(
    const __nv_bfloat16* __restrict__ Ah, const __nv_bfloat16* __restrict__ Al,
    const __nv_bfloat16* __restrict__ Bh, const __nv_bfloat16* __restrict__ Bl,
    float* __restrict__ C, const float* __restrict__ bias, int bn, int bm)
{
    extern __shared__ __nv_bfloat16 sm[];
    const uint32_t su = smem_u32(sm);
    const int t    = threadIdx.x;
    const int wid  = t >> 5;
    const int lane = t & 31;
    const int g    = lane >> 2;
    const int tg   = lane & 3;
    const int mo   = (wid & 1) * 64;
    const int no   = (wid >> 1) * 32;
    const int rbA  = bm * 128, rbB = bn * 128;

    const int a_r = (lane & 15);
    const int a_c = (lane >> 4) << 3;
    const int b_r = ((lane >> 4) << 3) + (lane & 7);
    const int b_c = ((lane >> 3) & 1) << 3;

    float acc[4][4][4];
    #pragma unroll
    for (int mt = 0; mt < 4; ++mt)
        #pragma unroll
        for (int nt = 0; nt < 4; ++nt)
            #pragma unroll
            for (int r = 0; r < 4; ++r) acc[mt][nt][r] = 0.f;

    #pragma unroll
    for (int st = 0; st < 3; ++st) {
        gemm_issue_stage(su, st, st, Ah, Al, Bh, Bl, rbA, rbB, t);
        CP_COMMIT();
    }

    for (int kt = 0; kt < NKI; ++kt) {
        CP_WAIT(2);
        __syncthreads();
        if (kt + 3 < NKI)
            gemm_issue_stage(su, (kt+3) & 3, kt+3, Ah, Al, Bh, Bl, rbA, rbB, t);
        CP_COMMIT();

        const uint32_t buf = su + (kt & 3) * STAGE_B;
        const uint32_t tAh = buf;
        const uint32_t tAl = buf + TILE_BYTES;
        const uint32_t tBh = buf + 2*TILE_BYTES;
        const uint32_t tBl = buf + 3*TILE_BYTES;

        #pragma unroll
        for (int ks = 0; ks < 2; ++ks) {
            uint32_t aH[4][4], aL[4][4], bH[2][4], bL[2][4];
            #pragma unroll
            for (int mt = 0; mt < 4; ++mt) {
                uint32_t off = 2*((mo + mt*16 + a_r)*AROW + ks*16 + a_c);
                LDSM4(aH[mt][0], aH[mt][1], aH[mt][2], aH[mt][3], tAh + off);
                LDSM4(aL[mt][0], aL[mt][1], aL[mt][2], aL[mt][3], tAl + off);
            }
            #pragma unroll
            for (int np = 0; np < 2; ++np) {
                uint32_t off = 2*((no + np*16 + b_r)*AROW + ks*16 + b_c);
                LDSM4(bH[np][0], bH[np][1], bH[np][2], bH[np][3], tBh + off);
                LDSM4(bL[np][0], bL[np][1], bL[np][2], bL[np][3], tBl + off);
            }
            #pragma unroll
            for (int mt = 0; mt < 4; ++mt)
                #pragma unroll
                for (int np = 0; np < 2; ++np) {
                    mma16816(acc[mt][2*np],   aH[mt], &bH[np][0]);
                    mma16816(acc[mt][2*np],   aH[mt], &bL[np][0]);
                    mma16816(acc[mt][2*np],   aL[mt], &bH[np][0]);
                    mma16816(acc[mt][2*np+1], aH[mt], &bH[np][2]);
                    mma16816(acc[mt][2*np+1], aH[mt], &bL[np][2]);
                    mma16816(acc[mt][2*np+1], aL[mt], &bH[np][2]);
                }
        }
    }

    const int row0 = bm*128, col0 = bn*128;
    #pragma unroll
    for (int mt = 0; mt < 4; ++mt) {
        int r = row0 + mo + mt*16 + g;
        #pragma unroll
        for (int nt = 0; nt < 4; ++nt) {
            int c = col0 + no + nt*8 + 2*tg;
            float b0 = 0.f, b1 = 0.f;
            if (bias) { b0 = bias[c]; b1 = bias[c+1]; }
            float2 v0 = make_float2(acc[mt][nt][0] + b0, acc[mt][nt][1] + b1);
            float2 v1 = make_float2(acc[mt][nt][2] + b0, acc[mt][nt][3] + b1);
            *(float2*)&C[(size_t)r * DIM + c]     = v0;
            *(float2*)&C[(size_t)(r+8) * DIM + c] = v1;
        }
    }
}

__global__ __launch_bounds__(256, 1) void qkv_mma_kernel()
{
    const int z = blockIdx.z;
    float* C = (z == 0) ? g_q : (z == 1 ? g_k : g_v);
    gemm_mma_body(g_xh, g_xl, g_wh + (size_t)z*DD, g_wl + (size_t)z*DD,
                  C, nullptr, blockIdx.x, blockIdx.y);
}

__global__ __launch_bounds__(256, 1) void out_mma_kernel(
    float* __restrict__ out, const float* __restrict__ bo)
{
    gemm_mma_body(g_aoh, g_aol, g_wh + (size_t)3*DD, g_wl + (size_t)3*DD,
                  out, bo, blockIdx.x, blockIdx.y);
}

// ---------------- RoPE -> fp16 (q scaled) ----------------
__global__ void rope_f16_kernel(int which)
{
    const float* src = which ? g_k : g_q;
    __half* dst = which ? g_kf : g_qf;
    int idx = blockIdx.x * blockDim.x + threadIdx.x;
    int m   = idx >> 10;
    int rem = idx & 1023;
    int h   = rem >> 6;
    int j   = rem & 63;
    int s   = m & (SEQ - 1);
    float freq = exp2f(-(float)j * 0.20762050593045951f);
    float ang  = (float)s * freq;
    float sn, cs;
    sincosf(ang, &sn, &cs);
    size_t base = (size_t)m * DIM + h * HD + j;
    float t1 = src[base], t2 = src[base + 64];
    float r1 = t1 * cs - t2 * sn;
    float r2 = t2 * cs + t1 * sn;
    if (!which) { r1 *= 0.088388347648318447f; r2 *= 0.088388347648318447f; }
    dst[base]      = __float2half(r1);
    dst[base + 64] = __float2half(r2);
}

// ---------------- V transpose -> fp16: g_v[b,s][h,d] -> g_vtf[bh][d][s] ----------------
__global__ void vt_f16_kernel()
{
    __shared__ float tile[32][33];
    const int bh = blockIdx.z;
    const int b  = bh >> 4, h = bh & 15;
    const int s0 = blockIdx.x * 32;
    const int d0 = blockIdx.y * 32;
    const int tx = threadIdx.x, ty = threadIdx.y;

    #pragma unroll
    for (int i = 0; i < 4; ++i) {
        int s = s0 + ty + 8*i;
        tile[ty + 8*i][tx] = g_v[(size_t)(b*SEQ + s)*DIM + h*HD + d0 + tx];
    }
    __syncthreads();
    #pragma unroll
    for (int i = 0; i < 4; ++i) {
        int d = d0 + ty + 8*i;
        g_vtf[((size_t)bh*HD + d)*SEQ + s0 + tx] = __float2half(tile[tx][ty + 8*i]);
    }
}

// ---------------- fp16 flash attention, double-buffered K and V ----------------
__device__ __forceinline__ void flash_issue_tile(
    uint32_t dst, const __half* gsrc, int stride, int t)
{
    #pragma unroll
    for (int i = 0; i < 8; ++i) {
        int s = t + 256*i; int r = s >> 4; int c16 = (s & 15) * 16;
        CP_ASYNC16(dst + r*272 + c16, (const char*)gsrc + (size_t)r*stride*2 + c16);
    }
}

__global__ __launch_bounds__(256, 1) void flash_f16_kernel()
{
    extern __shared__ __half shf[];
    const uint32_t su = smem_u32(shf);
    const uint32_t sQ = su;
    const uint32_t sK0 = su + FT_B;
    const uint32_t sK1 = su + 2*FT_B;
    const uint32_t sV0 = su + 3*FT_B;
    const uint32_t sV1 = su + 4*FT_B;

    const int t    = threadIdx.x;
    const int wid  = t >> 5;
    const int lane = t & 31;
    const int g    = lane >> 2;
    const int tg   = lane & 3;

    const int qt = (int)gridDim.x - 1 - (int)blockIdx.x;
    const int bh = blockIdx.y;
    const int b  = bh >> 4, h = bh & 15;
    const size_t row_base = (size_t)(b * SEQ + qt * 128);

    const int a_r = (lane & 15);
    const int a_c = (lane >> 4) << 3;
    const int b_r = ((lane >> 4) << 3) + (lane & 7);
    const int b_c = ((lane >> 3) & 1) << 3;

    const __half* K0 = g_kf + (size_t)b*SEQ*DIM + h*HD;
    const __half* V0 = g_vtf + (size_t)bh*HD*SEQ;

    // prologue: Q; then {K(0),V(0)}
    flash_issue_tile(sQ, g_qf + row_base*DIM + h*HD, DIM, t);
    CP_COMMIT();
    flash_issue_tile(sK0, K0, DIM, t);
    flash_issue_tile(sV0, V0, SEQ, t);
    CP_COMMIT();
    CP_WAIT(0);
    __syncthreads();

    // Q fragments to registers
    uint32_t qF[8][4];
    #pragma unroll
    for (int ks = 0; ks < 8; ++ks) {
        uint32_t off = 2*((wid*16 + a_r)*SR + ks*16 + a_c);
        LDSM4(qF[ks][0], qF[ks][1], qF[ks][2], qF[ks][3], sQ + off);
    }

    float s_[16][4];
    float o_[16][4];
    float m_a = -1e30f, m_b = -1e30f, l_a = 0.f, l_b = 0.f;
    #pragma unroll
    for (int nt = 0; nt < 16; ++nt)
        #pragma unroll
        for (int r = 0; r < 4; ++r) o_[nt][r] = 0.f;

    for (int jt = 0; jt <= qt; ++jt) {
        // prefetch next K and V
        if (jt < qt) {
            uint32_t kb = ((jt+1) & 1) ? sK1 : sK0;
            uint32_t vb = ((jt+1) & 1) ? sV1 : sV0;
            flash_issue_tile(kb, K0 + (size_t)(jt+1)*128*DIM, DIM, t);
            flash_issue_tile(vb, V0 + (size_t)(jt+1)*128, SEQ, t);
        }
        CP_COMMIT();
        CP_WAIT(1);      // K(jt), V(jt) resident
        __syncthreads();

        const uint32_t sK = (jt & 1) ? sK1 : sK0;
        const uint32_t sV = (jt & 1) ? sV1 : sV0;

        // S = Q K^T
        #pragma unroll
        for (int nt = 0; nt < 16; ++nt)
            #pragma unroll
            for (int r = 0; r < 4; ++r) s_[nt][r] = 0.f;

        #pragma unroll
        for (int ks = 0; ks < 8; ++ks) {
            #pragma unroll
            for (int np = 0; np < 8; ++np) {
                uint32_t bF[4];
                uint32_t offB = 2*((np*16 + b_r)*SR + ks*16 + b_c);
                LDSM4(bF[0], bF[1], bF[2], bF[3], sK + offB);
                mma16816h(s_[2*np],   qF[ks], &bF[0]);
                mma16816h(s_[2*np+1], qF[ks], &bF[2]);
            }
        }

        if (jt == qt) {
            const int ra = wid*16 + g, rb2 = ra + 8;
            #pragma unroll
            for (int nt = 0; nt < 16; ++nt) {
                int c0 = nt*8 + 2*tg;
                if (c0     > ra)  s_[nt][0] = -1e30f;
                if (c0 + 1 > ra)  s_[nt][1] = -1e30f;
                if (c0     > rb2) s_[nt][2] = -1e30f;
                if (c0 + 1 > rb2) s_[nt][3] = -1e30f;
            }
        }

        // online softmax
        {
            float mxa = -1e30f, mxb = -1e30f;
            #pragma unroll
            for (int nt = 0; nt < 16; ++nt) {
                mxa = fmaxf(mxa, fmaxf(s_[nt][0], s_[nt][1]));
                mxb = fmaxf(mxb, fmaxf(s_[nt][2], s_[nt][3]));
            }
            #pragma unroll
            for (int w = 1; w < 4; w <<= 1) {
                mxa = fmaxf(mxa, __shfl_xor_sync(0xffffffffu, mxa, w));
                mxb = fmaxf(mxb, __shfl_xor_sync(0xffffffffu, mxb, w));
            }
            float mna = fmaxf(m_a, mxa), mnb = fmaxf(m_b, mxb);
            float ca = __expf(m_a - mna), cb = __expf(m_b - mnb);
            m_a = mna; m_b = mnb;
            float sa = 0.f, sb = 0.f;
            #pragma unroll
            for (int nt = 0; nt < 16; ++nt) {
                s_[nt][0] = __expf(s_[nt][0] - mna);
                s_[nt][1] = __expf(s_[nt][1] - mna);
                s_[nt][2] = __expf(s_[nt][2] - mnb);
                s_[nt][3] = __expf(s_[nt][3] - mnb);
                sa += s_[nt][0] + s_[nt][1];
                sb += s_[nt][2] + s_[nt][3];
            }
            #pragma unroll
            for (int w = 1; w < 4; w <<= 1) {
                sa += __shfl_xor_sync(0xffffffffu, sa, w);
                sb += __shfl_xor_sync(0xffffffffu, sb, w);
            }
            l_a = l_a * ca + sa;
            l_b = l_b * cb + sb;
            #pragma unroll
            for (int nt = 0; nt < 16; ++nt) {
                o_[nt][0] *= ca; o_[nt][1] *= ca;
                o_[nt][2] *= cb; o_[nt][3] *= cb;
            }
        }

        // O += P V
        #pragma unroll
        for (int kk = 0; kk < 8; ++kk) {
            uint32_t aP[4];
            aP[0] = packh(s_[2*kk][0],   s_[2*kk][1]);
            aP[1] = packh(s_[2*kk][2],   s_[2*kk][3]);
            aP[2] = packh(s_[2*kk+1][0], s_[2*kk+1][1]);
            aP[3] = packh(s_[2*kk+1][2], s_[2*kk+1][3]);
            #pragma unroll
            for (int np = 0; np < 8; ++np) {
                uint32_t bF[4];
                uint32_t offB = 2*((np*16 + b_r)*SR + kk*16 + b_c);
                LDSM4(bF[0], bF[1], bF[2], bF[3], sV + offB);
                mma16816h(o_[2*np],   aP, &bF[0]);
                mma16816h(o_[2*np+1], aP, &bF[2]);
            }
        }
        __syncthreads();   // all reads of K(jt),V(jt) done before next prefetch
    }

    // epilogue: O /= l, write bf16 hi/lo split (for 3-term out-projection)
    {
        float ia = 1.f / l_a, ib = 1.f / l_b;
        const int ra = wid*16 + g;
        __nv_bfloat16* Oh = g_aoh + row_base * DIM + h * HD;
        __nv_bfloat16* Ol = g_aol + row_base * DIM + h * HD;
        #pragma unroll
        for (int nt = 0; nt < 16; ++nt) {
            int c = nt*8 + 2*tg;
            uint32_t ph, pl;
            split2(o_[nt][0]*ia, o_[nt][1]*ia, ph, pl);
            *(uint32_t*)(Oh + (size_t)ra*DIM + c) = ph;
            *(uint32_t*)(Ol + (size_t)ra*DIM + c) = pl;
            split2(o_[nt][2]*ib, o_[nt][3]*ib, ph, pl);
            *(uint32_t*)(Oh + (size_t)(ra+8)*DIM + c) = ph;
            *(uint32_t*)(Ol + (size_t)(ra+8)*DIM + c) = pl;
        }
    }
}

// ---------------------------------------------------------------------------
extern "C" void kernel_launch(void* const* d_in, const int* in_sizes, int n_in,
                              void* d_out, int out_size)
{
    const float* x  = (const float*)d_in[0];
    const float* Wq = (const float*)d_in[1];
    const float* Wk = (const float*)d_in[2];
    const float* Wv = (const float*)d_in[3];
    const float* Wo = (const float*)d_in[4];
    const float* bo = (const float*)d_in[5];
    float* out = (float*)d_out;

    cudaFuncSetAttribute(flash_f16_kernel,
        cudaFuncAttributeMaxDynamicSharedMemorySize, FLASH_SMEM);
    cudaFuncSetAttribute(qkv_mma_kernel,
        cudaFuncAttributeMaxDynamicSharedMemorySize, GEMM_SMEM);
    cudaFuncSetAttribute(out_mma_kernel,
        cudaFuncAttributeMaxDynamicSharedMemorySize, GEMM_SMEM);

    split_bf16_kernel<<<(MROWS*DIM/4)/256, 256>>>(x,  0, MROWS*DIM/4);
    split_bf16_kernel<<<(DD/4)/256, 256>>>(Wq, 1, DD/4);
    split_bf16_kernel<<<(DD/4)/256, 256>>>(Wk, 2, DD/4);
    split_bf16_kernel<<<(DD/4)/256, 256>>>(Wv, 3, DD/4);
    split_bf16_kernel<<<(DD/4)/256, 256>>>(Wo, 4, DD/4);

    dim3 gq(DIM/128, MROWS/128, 3);
    qkv_mma_kernel<<<gq, 256, GEMM_SMEM>>>();

    int rope_blocks = (MROWS * 1024) / 256;
    rope_f16_kernel<<<rope_blocks, 256>>>(0);
    rope_f16_kernel<<<rope_blocks, 256>>>(1);
    vt_f16_kernel<<<dim3(SEQ/32, HD/32, BATCH*NHEADS), dim3(32, 8)>>>();

    dim3 gf(SEQ/128, BATCH*NHEADS);
    flash_f16_kernel<<<gf, 256, FLASH_SMEM>>>();

    dim3 go(DIM/128, MROWS/128);
    out_mma_kernel<<<go, 256, GEMM_SMEM>>>(out, bo);
}

// round 7
// speedup vs baseline: 7.0956x; 2.2480x over previous
#include <cuda_runtime.h>
#include <cuda_bf16.h>
#include <cuda_fp16.h>
#include <math.h>
#include <stdint.h>

#define DIM 2048
#define NHEADS 16
#define HD 128
#define BATCH 4
#define SEQ 2048
#define MROWS (BATCH*SEQ)   // 8192
#define DD (DIM*DIM)

// GEMM tiling (fp16, 1-term)
#define KT 32               // halves of K per smem stage
#define NKI (DIM/KT)        // 64
#define AROW 40             // smem row: 32 halves + 8 pad (80 B)
#define TILE_E (128*AROW)
#define TILE_BYTES (TILE_E*2)          // 10240
#define STAGE_B (2*TILE_BYTES)         // 20480 (A, B)
#define GEMM_SMEM (4*STAGE_B)          // 81920

// flash smem
#define SR 136
#define FT_E (128*SR)
#define FT_B (FT_E*2)                   // 34816
#define FLASH_SMEM (5*FT_B)             // 174080: Q, K0, K1, V0, V1

// ---------------- scratch ----------------
__device__ float g_q [MROWS*DIM];
__device__ float g_k [MROWS*DIM];
__device__ float g_v [MROWS*DIM];
__device__ __half g_xf [MROWS*DIM];
__device__ __half g_wf [4*DD];
__device__ __half g_qf [MROWS*DIM];
__device__ __half g_kf [MROWS*DIM];
__device__ __half g_vtf[MROWS*DIM];   // [bh][d][s]
__device__ __half g_aof[MROWS*DIM];

// ---------------- helpers ----------------
__device__ __forceinline__ uint32_t smem_u32(const void* p) {
    uint32_t a;
    asm("{ .reg .u64 t; cvta.to.shared.u64 t, %1; cvt.u32.u64 %0, t; }" : "=r"(a) : "l"(p));
    return a;
}
#define LDSM4(r0,r1,r2,r3,addr) \
    asm volatile("ldmatrix.sync.aligned.m8n8.x4.shared.b16 {%0,%1,%2,%3}, [%4];" \
        : "=r"(r0), "=r"(r1), "=r"(r2), "=r"(r3) : "r"(addr))
#define CP_ASYNC16(sa, ga) \
    asm volatile("cp.async.cg.shared.global [%0], [%1], 16;" :: "r"(sa), "l"(ga))
#define CP_COMMIT() asm volatile("cp.async.commit_group;" ::: "memory")
#define CP_WAIT(n)  asm volatile("cp.async.wait_group %0;" :: "n"(n) : "memory")

__device__ __forceinline__ void mma16816h(float* d, const uint32_t* a, const uint32_t* b)
{
    asm volatile(
        "mma.sync.aligned.m16n8k16.row.col.f32.f16.f16.f32 "
        "{%0,%1,%2,%3}, {%4,%5,%6,%7}, {%8,%9}, {%0,%1,%2,%3};"
        : "+f"(d[0]), "+f"(d[1]), "+f"(d[2]), "+f"(d[3])
        : "r"(a[0]), "r"(a[1]), "r"(a[2]), "r"(a[3]), "r"(b[0]), "r"(b[1]));
}
__device__ __forceinline__ uint32_t packh(float x, float y) {
    __half2 h = __floats2half2_rn(x, y);
    return *(uint32_t*)&h;
}

// ---------------- fp32 -> fp16 conversion ----------------
// sel 0: x -> g_xf ; 1..4: W -> g_wf slot (sel-1)
__global__ void to_f16_kernel(const float* __restrict__ in, int sel, int n4)
{
    int i = blockIdx.x * blockDim.x + threadIdx.x;
    if (i >= n4) return;
    __half* dst = (sel == 0) ? g_xf : (g_wf + (size_t)(sel - 1) * DD);
    float4 v = ((const float4*)in)[i];
    __half2* d2 = (__half2*)dst;
    d2[i*2+0] = __floats2half2_rn(v.x, v.y);
    d2[i*2+1] = __floats2half2_rn(v.z, v.w);
}

// ---------------- pipelined fp16 NT GEMM on mma.sync ----------------
__device__ __forceinline__ void gemm_issue_stage(
    uint32_t su, int slot, int kt,
    const __half* A, const __half* B, int rbA, int rbB, int t)
{
    const int ko = kt * KT;
    const uint32_t base = su + slot * STAGE_B;
    #pragma unroll
    for (int i = 0; i < 2; ++i) {
        int s = t + 256*i; int r = s >> 2, v = s & 3;
        CP_ASYNC16(base + r*80 + v*16,
                   A + (size_t)(rbA+r)*DIM + ko + v*8);
        CP_ASYNC16(base + TILE_BYTES + r*80 + v*16,
                   B + (size_t)(rbB+r)*DIM + ko + v*8);
    }
}

__device__ __forceinline__ void gemm_mma_body(
    const __half* __restrict__ A, const __half* __restrict__ B,
    float* __restrict__ C, const float* __restrict__ bias, int bn, int bm)
{
    extern __shared__ __half sm[];
    const uint32_t su = smem_u32(sm);
    const int t    = threadIdx.x;
    const int wid  = t >> 5;
    const int lane = t & 31;
    const int g    = lane >> 2;
    const int tg   = lane & 3;
    const int mo   = (wid & 1) * 64;
    const int no   = (wid >> 1) * 32;
    const int rbA  = bm * 128, rbB = bn * 128;

    const int a_r = (lane & 15);
    const int a_c = (lane >> 4) << 3;
    const int b_r = ((lane >> 4) << 3) + (lane & 7);
    const int b_c = ((lane >> 3) & 1) << 3;

    float acc[4][4][4];
    #pragma unroll
    for (int mt = 0; mt < 4; ++mt)
        #pragma unroll
        for (int nt = 0; nt < 4; ++nt)
            #pragma unroll
            for (int r = 0; r < 4; ++r) acc[mt][nt][r] = 0.f;

    #pragma unroll
    for (int st = 0; st < 3; ++st) {
        gemm_issue_stage(su, st, st, A, B, rbA, rbB, t);
        CP_COMMIT();
    }

    for (int kt = 0; kt < NKI; ++kt) {
        CP_WAIT(2);
        __syncthreads();
        if (kt + 3 < NKI)
            gemm_issue_stage(su, (kt+3) & 3, kt+3, A, B, rbA, rbB, t);
        CP_COMMIT();

        const uint32_t tA = su + (kt & 3) * STAGE_B;
        const uint32_t tB = tA + TILE_BYTES;

        #pragma unroll
        for (int ks = 0; ks < 2; ++ks) {
            uint32_t aF[4][4], bF[2][4];
            #pragma unroll
            for (int mt = 0; mt < 4; ++mt) {
                uint32_t off = 2*((mo + mt*16 + a_r)*AROW + ks*16 + a_c);
                LDSM4(aF[mt][0], aF[mt][1], aF[mt][2], aF[mt][3], tA + off);
            }
            #pragma unroll
            for (int np = 0; np < 2; ++np) {
                uint32_t off = 2*((no + np*16 + b_r)*AROW + ks*16 + b_c);
                LDSM4(bF[np][0], bF[np][1], bF[np][2], bF[np][3], tB + off);
            }
            #pragma unroll
            for (int mt = 0; mt < 4; ++mt)
                #pragma unroll
                for (int np = 0; np < 2; ++np) {
                    mma16816h(acc[mt][2*np],   aF[mt], &bF[np][0]);
                    mma16816h(acc[mt][2*np+1], aF[mt], &bF[np][2]);
                }
        }
    }

    const int row0 = bm*128, col0 = bn*128;
    #pragma unroll
    for (int mt = 0; mt < 4; ++mt) {
        int r = row0 + mo + mt*16 + g;
        #pragma unroll
        for (int nt = 0; nt < 4; ++nt) {
            int c = col0 + no + nt*8 + 2*tg;
            float b0 = 0.f, b1 = 0.f;
            if (bias) { b0 = bias[c]; b1 = bias[c+1]; }
            float2 v0 = make_float2(acc[mt][nt][0] + b0, acc[mt][nt][1] + b1);
            float2 v1 = make_float2(acc[mt][nt][2] + b0, acc[mt][nt][3] + b1);
            *(float2*)&C[(size_t)r * DIM + c]     = v0;
            *(float2*)&C[(size_t)(r+8) * DIM + c] = v1;
        }
    }
}

__global__ __launch_bounds__(256, 2) void qkv_mma_kernel()
{
    const int z = blockIdx.z;
    float* C = (z == 0) ? g_q : (z == 1 ? g_k : g_v);
    gemm_mma_body(g_xf, g_wf + (size_t)z*DD, C, nullptr, blockIdx.x, blockIdx.y);
}

__global__ __launch_bounds__(256, 2) void out_mma_kernel(
    float* __restrict__ out, const float* __restrict__ bo)
{
    gemm_mma_body(g_aof, g_wf + (size_t)3*DD, out, bo, blockIdx.x, blockIdx.y);
}

// ---------------- RoPE -> fp16 (q scaled) ----------------
__global__ void rope_f16_kernel(int which)
{
    const float* src = which ? g_k : g_q;
    __half* dst = which ? g_kf : g_qf;
    int idx = blockIdx.x * blockDim.x + threadIdx.x;
    int m   = idx >> 10;
    int rem = idx & 1023;
    int h   = rem >> 6;
    int j   = rem & 63;
    int s   = m & (SEQ - 1);
    float freq = exp2f(-(float)j * 0.20762050593045951f);
    float ang  = (float)s * freq;
    float sn, cs;
    sincosf(ang, &sn, &cs);
    size_t base = (size_t)m * DIM + h * HD + j;
    float t1 = src[base], t2 = src[base + 64];
    float r1 = t1 * cs - t2 * sn;
    float r2 = t2 * cs + t1 * sn;
    if (!which) { r1 *= 0.088388347648318447f; r2 *= 0.088388347648318447f; }
    dst[base]      = __float2half(r1);
    dst[base + 64] = __float2half(r2);
}

// ---------------- V transpose -> fp16 ----------------
__global__ void vt_f16_kernel()
{
    __shared__ float tile[32][33];
    const int bh = blockIdx.z;
    const int b  = bh >> 4, h = bh & 15;
    const int s0 = blockIdx.x * 32;
    const int d0 = blockIdx.y * 32;
    const int tx = threadIdx.x, ty = threadIdx.y;

    #pragma unroll
    for (int i = 0; i < 4; ++i) {
        int s = s0 + ty + 8*i;
        tile[ty + 8*i][tx] = g_v[(size_t)(b*SEQ + s)*DIM + h*HD + d0 + tx];
    }
    __syncthreads();
    #pragma unroll
    for (int i = 0; i < 4; ++i) {
        int d = d0 + ty + 8*i;
        g_vtf[((size_t)bh*HD + d)*SEQ + s0 + tx] = __float2half(tile[tx][ty + 8*i]);
    }
}

// ---------------- fp16 flash attention, double-buffered K and V ----------------
__device__ __forceinline__ void flash_issue_tile(
    uint32_t dst, const __half* gsrc, int stride, int t)
{
    #pragma unroll
    for (int i = 0; i < 8; ++i) {
        int s = t + 256*i; int r = s >> 4; int c16 = (s & 15) * 16;
        CP_ASYNC16(dst + r*272 + c16, (const char*)gsrc + (size_t)r*stride*2 + c16);
    }
}

__global__ __launch_bounds__(256, 1) void flash_f16_kernel()
{
    extern __shared__ __half shf[];
    const uint32_t su = smem_u32(shf);
    const uint32_t sQ = su;
    const uint32_t sK0 = su + FT_B;
    const uint32_t sK1 = su + 2*FT_B;
    const uint32_t sV0 = su + 3*FT_B;
    const uint32_t sV1 = su + 4*FT_B;

    const int t    = threadIdx.x;
    const int wid  = t >> 5;
    const int lane = t & 31;
    const int g    = lane >> 2;
    const int tg   = lane & 3;

    const int qt = (int)gridDim.x - 1 - (int)blockIdx.x;
    const int bh = blockIdx.y;
    const int b  = bh >> 4, h = bh & 15;
    const size_t row_base = (size_t)(b * SEQ + qt * 128);

    const int a_r = (lane & 15);
    const int a_c = (lane >> 4) << 3;
    const int b_r = ((lane >> 4) << 3) + (lane & 7);
    const int b_c = ((lane >> 3) & 1) << 3;

    const __half* K0 = g_kf + (size_t)b*SEQ*DIM + h*HD;
    const __half* V0 = g_vtf + (size_t)bh*HD*SEQ;

    flash_issue_tile(sQ, g_qf + row_base*DIM + h*HD, DIM, t);
    CP_COMMIT();
    flash_issue_tile(sK0, K0, DIM, t);
    flash_issue_tile(sV0, V0, SEQ, t);
    CP_COMMIT();
    CP_WAIT(0);
    __syncthreads();

    uint32_t qF[8][4];
    #pragma unroll
    for (int ks = 0; ks < 8; ++ks) {
        uint32_t off = 2*((wid*16 + a_r)*SR + ks*16 + a_c);
        LDSM4(qF[ks][0], qF[ks][1], qF[ks][2], qF[ks][3], sQ + off);
    }

    float s_[16][4];
    float o_[16][4];
    float m_a = -1e30f, m_b = -1e30f, l_a = 0.f, l_b = 0.f;
    #pragma unroll
    for (int nt = 0; nt < 16; ++nt)
        #pragma unroll
        for (int r = 0; r < 4; ++r) o_[nt][r] = 0.f;

    for (int jt = 0; jt <= qt; ++jt) {
        if (jt < qt) {
            uint32_t kb = ((jt+1) & 1) ? sK1 : sK0;
            uint32_t vb = ((jt+1) & 1) ? sV1 : sV0;
            flash_issue_tile(kb, K0 + (size_t)(jt+1)*128*DIM, DIM, t);
            flash_issue_tile(vb, V0 + (size_t)(jt+1)*128, SEQ, t);
        }
        CP_COMMIT();
        CP_WAIT(1);
        __syncthreads();

        const uint32_t sK = (jt & 1) ? sK1 : sK0;
        const uint32_t sV = (jt & 1) ? sV1 : sV0;

        #pragma unroll
        for (int nt = 0; nt < 16; ++nt)
            #pragma unroll
            for (int r = 0; r < 4; ++r) s_[nt][r] = 0.f;

        #pragma unroll
        for (int ks = 0; ks < 8; ++ks) {
            #pragma unroll
            for (int np = 0; np < 8; ++np) {
                uint32_t bF[4];
                uint32_t offB = 2*((np*16 + b_r)*SR + ks*16 + b_c);
                LDSM4(bF[0], bF[1], bF[2], bF[3], sK + offB);
                mma16816h(s_[2*np],   qF[ks], &bF[0]);
                mma16816h(s_[2*np+1], qF[ks], &bF[2]);
            }
        }

        if (jt == qt) {
            const int ra = wid*16 + g, rb2 = ra + 8;
            #pragma unroll
            for (int nt = 0; nt < 16; ++nt) {
                int c0 = nt*8 + 2*tg;
                if (c0     > ra)  s_[nt][0] = -1e30f;
                if (c0 + 1 > ra)  s_[nt][1] = -1e30f;
                if (c0     > rb2) s_[nt][2] = -1e30f;
                if (c0 + 1 > rb2) s_[nt][3] = -1e30f;
            }
        }

        {
            float mxa = -1e30f, mxb = -1e30f;
            #pragma unroll
            for (int nt = 0; nt < 16; ++nt) {
                mxa = fmaxf(mxa, fmaxf(s_[nt][0], s_[nt][1]));
                mxb = fmaxf(mxb, fmaxf(s_[nt][2], s_[nt][3]));
            }
            #pragma unroll
            for (int w = 1; w < 4; w <<= 1) {
                mxa = fmaxf(mxa, __shfl_xor_sync(0xffffffffu, mxa, w));
                mxb = fmaxf(mxb, __shfl_xor_sync(0xffffffffu, mxb, w));
            }
            float mna = fmaxf(m_a, mxa), mnb = fmaxf(m_b, mxb);
            float ca = __expf(m_a - mna), cb = __expf(m_b - mnb);
            m_a = mna; m_b = mnb;
            float sa = 0.f, sb = 0.f;
            #pragma unroll
            for (int nt = 0; nt < 16; ++nt) {
                s_[nt][0] = __expf(s_[nt][0] - mna);
                s_[nt][1] = __expf(s_[nt][1] - mna);
                s_[nt][2] = __expf(s_[nt][2] - mnb);
                s_[nt][3] = __expf(s_[nt][3] - mnb);
                sa += s_[nt][0] + s_[nt][1];
                sb += s_[nt][2] + s_[nt][3];
            }
            #pragma unroll
            for (int w = 1; w < 4; w <<= 1) {
                sa += __shfl_xor_sync(0xffffffffu, sa, w);
                sb += __shfl_xor_sync(0xffffffffu, sb, w);
            }
            l_a = l_a * ca + sa;
            l_b = l_b * cb + sb;
            #pragma unroll
            for (int nt = 0; nt < 16; ++nt) {
                o_[nt][0] *= ca; o_[nt][1] *= ca;
                o_[nt][2] *= cb; o_[nt][3] *= cb;
            }
        }

        #pragma unroll
        for (int kk = 0; kk < 8; ++kk) {
            uint32_t aP[4];
            aP[0] = packh(s_[2*kk][0],   s_[2*kk][1]);
            aP[1] = packh(s_[2*kk][2],   s_[2*kk][3]);
            aP[2] = packh(s_[2*kk+1][0], s_[2*kk+1][1]);
            aP[3] = packh(s_[2*kk+1][2], s_[2*kk+1][3]);
            #pragma unroll
            for (int np = 0; np < 8; ++np) {
                uint32_t bF[4];
                uint32_t offB = 2*((np*16 + b_r)*SR + kk*16 + b_c);
                LDSM4(bF[0], bF[1], bF[2], bF[3], sV + offB);
                mma16816h(o_[2*np],   aP, &bF[0]);
                mma16816h(o_[2*np+1], aP, &bF[2]);
            }
        }
        __syncthreads();
    }

    // epilogue: O /= l, write fp16 directly (out-projection input)
    {
        float ia = 1.f / l_a, ib = 1.f / l_b;
        const int ra = wid*16 + g;
        __half* O = g_aof + row_base * DIM + h * HD;
        #pragma unroll
        for (int nt = 0; nt < 16; ++nt) {
            int c = nt*8 + 2*tg;
            *(uint32_t*)(O + (size_t)ra*DIM + c)     = packh(o_[nt][0]*ia, o_[nt][1]*ia);
            *(uint32_t*)(O + (size_t)(ra+8)*DIM + c) = packh(o_[nt][2]*ib, o_[nt][3]*ib);
        }
    }
}

// ---------------------------------------------------------------------------
extern "C" void kernel_launch(void* const* d_in, const int* in_sizes, int n_in,
                              void* d_out, int out_size)
{
    const float* x  = (const float*)d_in[0];
    const float* Wq = (const float*)d_in[1];
    const float* Wk = (const float*)d_in[2];
    const float* Wv = (const float*)d_in[3];
    const float* Wo = (const float*)d_in[4];
    const float* bo = (const float*)d_in[5];
    float* out = (float*)d_out;

    cudaFuncSetAttribute(flash_f16_kernel,
        cudaFuncAttributeMaxDynamicSharedMemorySize, FLASH_SMEM);
    cudaFuncSetAttribute(qkv_mma_kernel,
        cudaFuncAttributeMaxDynamicSharedMemorySize, GEMM_SMEM);
    cudaFuncSetAttribute(out_mma_kernel,
        cudaFuncAttributeMaxDynamicSharedMemorySize, GEMM_SMEM);

    to_f16_kernel<<<(MROWS*DIM/4)/256, 256>>>(x,  0, MROWS*DIM/4);
    to_f16_kernel<<<(DD/4)/256, 256>>>(Wq, 1, DD/4);
    to_f16_kernel<<<(DD/4)/256, 256>>>(Wk, 2, DD/4);
    to_f16_kernel<<<(DD/4)/256, 256>>>(Wv, 3, DD/4);
    to_f16_kernel<<<(DD/4)/256, 256>>>(Wo, 4, DD/4);

    dim3 gq(DIM/128, MROWS/128, 3);
    qkv_mma_kernel<<<gq, 256, GEMM_SMEM>>>();

    int rope_blocks = (MROWS * 1024) / 256;
    rope_f16_kernel<<<rope_blocks, 256>>>(0);
    rope_f16_kernel<<<rope_blocks, 256>>>(1);
    vt_f16_kernel<<<dim3(SEQ/32, HD/32, BATCH*NHEADS), dim3(32, 8)>>>();

    dim3 gf(SEQ/128, BATCH*NHEADS);
    flash_f16_kernel<<<gf, 256, FLASH_SMEM>>>();

    dim3 go(DIM/128, MROWS/128);
    out_mma_kernel<<<go, 256, GEMM_SMEM>>>(out, bo);
}

// round 8
// speedup vs baseline: 7.7382x; 1.0906x over previous
#include <cuda_runtime.h>
#include <cuda_fp16.h>
#include <math.h>
#include <stdint.h>

#define DIM 2048
#define NHEADS 16
#define HD 128
#define BATCH 4
#define SEQ 2048
#define MROWS (BATCH*SEQ)   // 8192
#define DD (DIM*DIM)

// GEMM tiling (fp16, 1-term)
#define KT 32               // halves of K per smem stage
#define NKI (DIM/KT)        // 64
#define AROW 40             // smem row: 32 halves + 8 pad (80 B)
#define TILE_E (128*AROW)
#define TILE_BYTES (TILE_E*2)          // 10240
#define STAGE_B (2*TILE_BYTES)         // 20480 (A, B)
#define GEMM_SMEM 81920                // 4 stages; also >= 128*129*4 staging

// flash smem
#define SR 136
#define FT_E (128*SR)
#define FT_B (FT_E*2)                   // 34816
#define FLASH_SMEM (5*FT_B)             // 174080: Q, K0, K1, V0, V1

// ---------------- scratch ----------------
__device__ __half g_xf [MROWS*DIM];
__device__ __half g_wf [4*DD];
__device__ __half g_qf [MROWS*DIM];
__device__ __half g_kf [MROWS*DIM];
__device__ __half g_vtf[MROWS*DIM];   // [bh][d][s]
__device__ __half g_aof[MROWS*DIM];

// ---------------- helpers ----------------
__device__ __forceinline__ uint32_t smem_u32(const void* p) {
    uint32_t a;
    asm("{ .reg .u64 t; cvta.to.shared.u64 t, %1; cvt.u32.u64 %0, t; }" : "=r"(a) : "l"(p));
    return a;
}
#define LDSM4(r0,r1,r2,r3,addr) \
    asm volatile("ldmatrix.sync.aligned.m8n8.x4.shared.b16 {%0,%1,%2,%3}, [%4];" \
        : "=r"(r0), "=r"(r1), "=r"(r2), "=r"(r3) : "r"(addr))
#define CP_ASYNC16(sa, ga) \
    asm volatile("cp.async.cg.shared.global [%0], [%1], 16;" :: "r"(sa), "l"(ga))
#define CP_COMMIT() asm volatile("cp.async.commit_group;" ::: "memory")
#define CP_WAIT(n)  asm volatile("cp.async.wait_group %0;" :: "n"(n) : "memory")

__device__ __forceinline__ void mma16816h(float* d, const uint32_t* a, const uint32_t* b)
{
    asm volatile(
        "mma.sync.aligned.m16n8k16.row.col.f32.f16.f16.f32 "
        "{%0,%1,%2,%3}, {%4,%5,%6,%7}, {%8,%9}, {%0,%1,%2,%3};"
        : "+f"(d[0]), "+f"(d[1]), "+f"(d[2]), "+f"(d[3])
        : "r"(a[0]), "r"(a[1]), "r"(a[2]), "r"(a[3]), "r"(b[0]), "r"(b[1]));
}
__device__ __forceinline__ uint32_t packh(float x, float y) {
    __half2 h = __floats2half2_rn(x, y);
    return *(uint32_t*)&h;
}

// ---------------- fp32 -> fp16 conversion ----------------
__global__ void to_f16_kernel(const float* __restrict__ in, int sel, int n4)
{
    int i = blockIdx.x * blockDim.x + threadIdx.x;
    if (i >= n4) return;
    __half* dst = (sel == 0) ? g_xf : (g_wf + (size_t)(sel - 1) * DD);
    float4 v = ((const float4*)in)[i];
    __half2* d2 = (__half2*)dst;
    d2[i*2+0] = __floats2half2_rn(v.x, v.y);
    d2[i*2+1] = __floats2half2_rn(v.z, v.w);
}

// ---------------- pipelined fp16 NT GEMM mainloop (shared) ----------------
__device__ __forceinline__ void gemm_issue_stage(
    uint32_t su, int slot, int kt,
    const __half* A, const __half* B, int rbA, int rbB, int t)
{
    const int ko = kt * KT;
    const uint32_t base = su + slot * STAGE_B;
    #pragma unroll
    for (int i = 0; i < 2; ++i) {
        int s = t + 256*i; int r = s >> 2, v = s & 3;
        CP_ASYNC16(base + r*80 + v*16,
                   A + (size_t)(rbA+r)*DIM + ko + v*8);
        CP_ASYNC16(base + TILE_BYTES + r*80 + v*16,
                   B + (size_t)(rbB+r)*DIM + ko + v*8);
    }
}

// computes 128x128 tile into acc[4][4][4]; warp layout 2m x 4n, warp tile 64x32
__device__ __forceinline__ void gemm_mainloop(
    const __half* __restrict__ A, const __half* __restrict__ B,
    int rbA, int rbB, float acc[4][4][4], uint32_t su)
{
    const int t    = threadIdx.x;
    const int wid  = t >> 5;
    const int lane = t & 31;
    const int mo   = (wid & 1) * 64;
    const int no   = (wid >> 1) * 32;

    const int a_r = (lane & 15);
    const int a_c = (lane >> 4) << 3;
    const int b_r = ((lane >> 4) << 3) + (lane & 7);
    const int b_c = ((lane >> 3) & 1) << 3;

    #pragma unroll
    for (int mt = 0; mt < 4; ++mt)
        #pragma unroll
        for (int nt = 0; nt < 4; ++nt)
            #pragma unroll
            for (int r = 0; r < 4; ++r) acc[mt][nt][r] = 0.f;

    #pragma unroll
    for (int st = 0; st < 3; ++st) {
        gemm_issue_stage(su, st, st, A, B, rbA, rbB, t);
        CP_COMMIT();
    }

    for (int kt = 0; kt < NKI; ++kt) {
        CP_WAIT(2);
        __syncthreads();
        if (kt + 3 < NKI)
            gemm_issue_stage(su, (kt+3) & 3, kt+3, A, B, rbA, rbB, t);
        CP_COMMIT();

        const uint32_t tA = su + (kt & 3) * STAGE_B;
        const uint32_t tB = tA + TILE_BYTES;

        #pragma unroll
        for (int ks = 0; ks < 2; ++ks) {
            uint32_t aF[4][4], bF[2][4];
            #pragma unroll
            for (int mt = 0; mt < 4; ++mt) {
                uint32_t off = 2*((mo + mt*16 + a_r)*AROW + ks*16 + a_c);
                LDSM4(aF[mt][0], aF[mt][1], aF[mt][2], aF[mt][3], tA + off);
            }
            #pragma unroll
            for (int np = 0; np < 2; ++np) {
                uint32_t off = 2*((no + np*16 + b_r)*AROW + ks*16 + b_c);
                LDSM4(bF[np][0], bF[np][1], bF[np][2], bF[np][3], tB + off);
            }
            #pragma unroll
            for (int mt = 0; mt < 4; ++mt)
                #pragma unroll
                for (int np = 0; np < 2; ++np) {
                    mma16816h(acc[mt][2*np],   aF[mt], &bF[np][0]);
                    mma16816h(acc[mt][2*np+1], aF[mt], &bF[np][2]);
                }
        }
    }
}

// ---------------- QKV GEMM with fused RoPE / V-transpose epilogue ----------------
// col block bn == head index (HD==128). z=0:q (rope+scale), 1:k (rope), 2:v (transpose)
#define SP 129   // fp32 staging pitch (conflict-free: 129 mod 32 = 1)
__global__ __launch_bounds__(256, 2) void qkv_mma_kernel()
{
    extern __shared__ __half sm[];
    const uint32_t su = smem_u32(sm);
    const int z  = blockIdx.z;
    const int bn = blockIdx.x;      // head
    const int bm = blockIdx.y;      // row block
    const int t  = threadIdx.x;
    const int wid = t >> 5, lane = t & 31;
    const int g = lane >> 2, tg = lane & 3;
    const int mo = (wid & 1) * 64, no = (wid >> 1) * 32;

    float acc[4][4][4];
    gemm_mainloop(g_xf, g_wf + (size_t)z*DD, bm*128, bn*128, acc, su);

    // stage fp32 tile to smem (pitch SP)
    __syncthreads();                     // all cp.async groups drained (empty tails)
    float* st = (float*)sm;
    #pragma unroll
    for (int mt = 0; mt < 4; ++mt) {
        int r = mo + mt*16 + g;
        #pragma unroll
        for (int nt = 0; nt < 4; ++nt) {
            int c = no + nt*8 + 2*tg;
            st[r*SP + c]     = acc[mt][nt][0];
            st[r*SP + c + 1] = acc[mt][nt][1];
            st[(r+8)*SP + c]     = acc[mt][nt][2];
            st[(r+8)*SP + c + 1] = acc[mt][nt][3];
        }
    }
    __syncthreads();

    const int row0 = bm * 128;
    const int b    = row0 / SEQ;         // constant per CTA (128 | SEQ)
    if (z < 2) {
        // RoPE: pairs (j, j+64), j in [0,64), 128 rows -> 8192 pairs
        __half* dst = (z == 0 ? g_qf : g_kf);
        #pragma unroll
        for (int i = 0; i < 32; ++i) {
            int idx = t + 256*i;         // 8192
            int r = idx >> 6, j = idx & 63;
            int s = (row0 + r) & (SEQ - 1);
            float freq = exp2f(-(float)j * 0.20762050593045951f);
            float sn, cs;
            sincosf((float)s * freq, &sn, &cs);
            float t1 = st[r*SP + j], t2 = st[r*SP + j + 64];
            float r1 = t1 * cs - t2 * sn;
            float r2 = t2 * cs + t1 * sn;
            if (z == 0) { r1 *= 0.088388347648318447f; r2 *= 0.088388347648318447f; }
            __half* p = dst + (size_t)(row0 + r) * DIM + bn * HD + j;
            p[0]  = __float2half(r1);
            p[64] = __float2half(r2);
        }
    } else {
        // V transpose: g_vtf[(b*NHEADS+bn)*HD + d][row0%SEQ + s_local]
        __half* dst = g_vtf + ((size_t)(b * NHEADS + bn) * HD) * SEQ + (row0 & (SEQ-1));
        #pragma unroll
        for (int i = 0; i < 64; ++i) {
            int idx = t + 256*i;         // 16384
            int d = idx >> 7, sl = idx & 127;
            dst[(size_t)d * SEQ + sl] = __float2half(st[sl*SP + d]);
        }
    }
}

// ---------------- out-projection GEMM (fp32 out + bias) ----------------
__global__ __launch_bounds__(256, 2) void out_mma_kernel(
    float* __restrict__ out, const float* __restrict__ bo)
{
    extern __shared__ __half sm[];
    const uint32_t su = smem_u32(sm);
    const int bn = blockIdx.x, bm = blockIdx.y;
    const int t = threadIdx.x;
    const int wid = t >> 5, lane = t & 31;
    const int g = lane >> 2, tg = lane & 3;
    const int mo = (wid & 1) * 64, no = (wid >> 1) * 32;

    float acc[4][4][4];
    gemm_mainloop(g_aof, g_wf + (size_t)3*DD, bm*128, bn*128, acc, su);

    const int row0 = bm*128, col0 = bn*128;
    #pragma unroll
    for (int mt = 0; mt < 4; ++mt) {
        int r = row0 + mo + mt*16 + g;
        #pragma unroll
        for (int nt = 0; nt < 4; ++nt) {
            int c = col0 + no + nt*8 + 2*tg;
            float b0 = bo[c], b1 = bo[c+1];
            float2 v0 = make_float2(acc[mt][nt][0] + b0, acc[mt][nt][1] + b1);
            float2 v1 = make_float2(acc[mt][nt][2] + b0, acc[mt][nt][3] + b1);
            *(float2*)&out[(size_t)r * DIM + c]     = v0;
            *(float2*)&out[(size_t)(r+8) * DIM + c] = v1;
        }
    }
}

// ---------------- fp16 flash attention, double-buffered K and V ----------------
__device__ __forceinline__ void flash_issue_tile(
    uint32_t dst, const __half* gsrc, int stride, int t)
{
    #pragma unroll
    for (int i = 0; i < 8; ++i) {
        int s = t + 256*i; int r = s >> 4; int c16 = (s & 15) * 16;
        CP_ASYNC16(dst + r*272 + c16, (const char*)gsrc + (size_t)r*stride*2 + c16);
    }
}

__global__ __launch_bounds__(256, 1) void flash_f16_kernel()
{
    extern __shared__ __half shf[];
    const uint32_t su = smem_u32(shf);
    const uint32_t sQ = su;
    const uint32_t sK0 = su + FT_B;
    const uint32_t sK1 = su + 2*FT_B;
    const uint32_t sV0 = su + 3*FT_B;
    const uint32_t sV1 = su + 4*FT_B;

    const int t    = threadIdx.x;
    const int wid  = t >> 5;
    const int lane = t & 31;
    const int g    = lane >> 2;
    const int tg   = lane & 3;

    const int qt = (int)gridDim.x - 1 - (int)blockIdx.x;
    const int bh = blockIdx.y;
    const int b  = bh >> 4, h = bh & 15;
    const size_t row_base = (size_t)(b * SEQ + qt * 128);

    const int a_r = (lane & 15);
    const int a_c = (lane >> 4) << 3;
    const int b_r = ((lane >> 4) << 3) + (lane & 7);
    const int b_c = ((lane >> 3) & 1) << 3;

    const __half* K0 = g_kf + (size_t)b*SEQ*DIM + h*HD;
    const __half* V0 = g_vtf + (size_t)bh*HD*SEQ;

    flash_issue_tile(sQ, g_qf + row_base*DIM + h*HD, DIM, t);
    CP_COMMIT();
    flash_issue_tile(sK0, K0, DIM, t);
    flash_issue_tile(sV0, V0, SEQ, t);
    CP_COMMIT();
    CP_WAIT(0);
    __syncthreads();

    uint32_t qF[8][4];
    #pragma unroll
    for (int ks = 0; ks < 8; ++ks) {
        uint32_t off = 2*((wid*16 + a_r)*SR + ks*16 + a_c);
        LDSM4(qF[ks][0], qF[ks][1], qF[ks][2], qF[ks][3], sQ + off);
    }

    float s_[16][4];
    float o_[16][4];
    float m_a = -1e30f, m_b = -1e30f, l_a = 0.f, l_b = 0.f;
    #pragma unroll
    for (int nt = 0; nt < 16; ++nt)
        #pragma unroll
        for (int r = 0; r < 4; ++r) o_[nt][r] = 0.f;

    for (int jt = 0; jt <= qt; ++jt) {
        if (jt < qt) {
            uint32_t kb = ((jt+1) & 1) ? sK1 : sK0;
            uint32_t vb = ((jt+1) & 1) ? sV1 : sV0;
            flash_issue_tile(kb, K0 + (size_t)(jt+1)*128*DIM, DIM, t);
            flash_issue_tile(vb, V0 + (size_t)(jt+1)*128, SEQ, t);
        }
        CP_COMMIT();
        CP_WAIT(1);
        __syncthreads();

        const uint32_t sK = (jt & 1) ? sK1 : sK0;
        const uint32_t sV = (jt & 1) ? sV1 : sV0;

        #pragma unroll
        for (int nt = 0; nt < 16; ++nt)
            #pragma unroll
            for (int r = 0; r < 4; ++r) s_[nt][r] = 0.f;

        #pragma unroll
        for (int ks = 0; ks < 8; ++ks) {
            #pragma unroll
            for (int np = 0; np < 8; ++np) {
                uint32_t bF[4];
                uint32_t offB = 2*((np*16 + b_r)*SR + ks*16 + b_c);
                LDSM4(bF[0], bF[1], bF[2], bF[3], sK + offB);
                mma16816h(s_[2*np],   qF[ks], &bF[0]);
                mma16816h(s_[2*np+1], qF[ks], &bF[2]);
            }
        }

        if (jt == qt) {
            const int ra = wid*16 + g, rb2 = ra + 8;
            #pragma unroll
            for (int nt = 0; nt < 16; ++nt) {
                int c0 = nt*8 + 2*tg;
                if (c0     > ra)  s_[nt][0] = -1e30f;
                if (c0 + 1 > ra)  s_[nt][1] = -1e30f;
                if (c0     > rb2) s_[nt][2] = -1e30f;
                if (c0 + 1 > rb2) s_[nt][3] = -1e30f;
            }
        }

        {
            float mxa = -1e30f, mxb = -1e30f;
            #pragma unroll
            for (int nt = 0; nt < 16; ++nt) {
                mxa = fmaxf(mxa, fmaxf(s_[nt][0], s_[nt][1]));
                mxb = fmaxf(mxb, fmaxf(s_[nt][2], s_[nt][3]));
            }
            #pragma unroll
            for (int w = 1; w < 4; w <<= 1) {
                mxa = fmaxf(mxa, __shfl_xor_sync(0xffffffffu, mxa, w));
                mxb = fmaxf(mxb, __shfl_xor_sync(0xffffffffu, mxb, w));
            }
            float mna = fmaxf(m_a, mxa), mnb = fmaxf(m_b, mxb);
            float ca = __expf(m_a - mna), cb = __expf(m_b - mnb);
            m_a = mna; m_b = mnb;
            float sa = 0.f, sb = 0.f;
            #pragma unroll
            for (int nt = 0; nt < 16; ++nt) {
                s_[nt][0] = __expf(s_[nt][0] - mna);
                s_[nt][1] = __expf(s_[nt][1] - mna);
                s_[nt][2] = __expf(s_[nt][2] - mnb);
                s_[nt][3] = __expf(s_[nt][3] - mnb);
                sa += s_[nt][0] + s_[nt][1];
                sb += s_[nt][2] + s_[nt][3];
            }
            #pragma unroll
            for (int w = 1; w < 4; w <<= 1) {
                sa += __shfl_xor_sync(0xffffffffu, sa, w);
                sb += __shfl_xor_sync(0xffffffffu, sb, w);
            }
            l_a = l_a * ca + sa;
            l_b = l_b * cb + sb;
            #pragma unroll
            for (int nt = 0; nt < 16; ++nt) {
                o_[nt][0] *= ca; o_[nt][1] *= ca;
                o_[nt][2] *= cb; o_[nt][3] *= cb;
            }
        }

        #pragma unroll
        for (int kk = 0; kk < 8; ++kk) {
            uint32_t aP[4];
            aP[0] = packh(s_[2*kk][0],   s_[2*kk][1]);
            aP[1] = packh(s_[2*kk][2],   s_[2*kk][3]);
            aP[2] = packh(s_[2*kk+1][0], s_[2*kk+1][1]);
            aP[3] = packh(s_[2*kk+1][2], s_[2*kk+1][3]);
            #pragma unroll
            for (int np = 0; np < 8; ++np) {
                uint32_t bF[4];
                uint32_t offB = 2*((np*16 + b_r)*SR + kk*16 + b_c);
                LDSM4(bF[0], bF[1], bF[2], bF[3], sV + offB);
                mma16816h(o_[2*np],   aP, &bF[0]);
                mma16816h(o_[2*np+1], aP, &bF[2]);
            }
        }
        __syncthreads();
    }

    {
        float ia = 1.f / l_a, ib = 1.f / l_b;
        const int ra = wid*16 + g;
        __half* O = g_aof + row_base * DIM + h * HD;
        #pragma unroll
        for (int nt = 0; nt < 16; ++nt) {
            int c = nt*8 + 2*tg;
            *(uint32_t*)(O + (size_t)ra*DIM + c)     = packh(o_[nt][0]*ia, o_[nt][1]*ia);
            *(uint32_t*)(O + (size_t)(ra+8)*DIM + c) = packh(o_[nt][2]*ib, o_[nt][3]*ib);
        }
    }
}

// ---------------------------------------------------------------------------
extern "C" void kernel_launch(void* const* d_in, const int* in_sizes, int n_in,
                              void* d_out, int out_size)
{
    const float* x  = (const float*)d_in[0];
    const float* Wq = (const float*)d_in[1];
    const float* Wk = (const float*)d_in[2];
    const float* Wv = (const float*)d_in[3];
    const float* Wo = (const float*)d_in[4];
    const float* bo = (const float*)d_in[5];
    float* out = (float*)d_out;

    cudaFuncSetAttribute(flash_f16_kernel,
        cudaFuncAttributeMaxDynamicSharedMemorySize, FLASH_SMEM);
    cudaFuncSetAttribute(qkv_mma_kernel,
        cudaFuncAttributeMaxDynamicSharedMemorySize, GEMM_SMEM);
    cudaFuncSetAttribute(out_mma_kernel,
        cudaFuncAttributeMaxDynamicSharedMemorySize, GEMM_SMEM);

    to_f16_kernel<<<(MROWS*DIM/4)/256, 256>>>(x,  0, MROWS*DIM/4);
    to_f16_kernel<<<(DD/4)/256, 256>>>(Wq, 1, DD/4);
    to_f16_kernel<<<(DD/4)/256, 256>>>(Wk, 2, DD/4);
    to_f16_kernel<<<(DD/4)/256, 256>>>(Wv, 3, DD/4);
    to_f16_kernel<<<(DD/4)/256, 256>>>(Wo, 4, DD/4);

    // QKV projections with fused RoPE / V-transpose epilogues
    dim3 gq(DIM/128, MROWS/128, 3);
    qkv_mma_kernel<<<gq, 256, GEMM_SMEM>>>();

    // flash attention
    dim3 gf(SEQ/128, BATCH*NHEADS);
    flash_f16_kernel<<<gf, 256, FLASH_SMEM>>>();

    // output projection
    dim3 go(DIM/128, MROWS/128);
    out_mma_kernel<<<go, 256, GEMM_SMEM>>>(out, bo);
}